// round 14
// baseline (speedup 1.0000x reference)
#include <cuda_runtime.h>
#include <cuda_fp16.h>
#include <stdint.h>

#define NPIX 32768            // B*H*W
#define QKVC 768

// Scratch (device globals; 16B-aligned)
__device__ __align__(16) __half g_qh[NPIX * QKVC];  // qkv fp16, [pixel][q|k|v]
__device__ __align__(16) __half g_bh[NPIX * 256];   // attn out fp16, [n][256]
__device__ __align__(16) __half g_wfh[1024 * 256];  // fused conv W fp16, [m][k]
__device__ __align__(16) __half g_wqh[QKVC * 256];  // qkv W fp16 (q pre-scaled), [m][k]
__device__ __align__(16) __half g_xh[256 * NPIX];   // x fp16, [k][n]
__device__ float g_bf[1024];

// ---------------------------------------------------------------------------
// helpers (non-arch-specific PTX only: cp.async / ldmatrix / mma.sync)
// ---------------------------------------------------------------------------
__device__ __forceinline__ uint32_t smem_u32(const void* p) {
    uint32_t a;
    asm("{ .reg .u64 t; cvta.to.shared.u64 t, %1; cvt.u32.u64 %0, t; }" : "=r"(a) : "l"(p));
    return a;
}
__device__ __forceinline__ void cp16(uint32_t d, const void* s) {
    asm volatile("cp.async.cg.shared.global [%0], [%1], 16;" :: "r"(d), "l"(s));
}
__device__ __forceinline__ void cp16z(uint32_t d, const void* s, uint32_t sz) {
    asm volatile("cp.async.cg.shared.global [%0], [%1], 16, %2;" :: "r"(d), "l"(s), "r"(sz));
}
#define CP_COMMIT() asm volatile("cp.async.commit_group;")
#define CP_WAIT1()  asm volatile("cp.async.wait_group 1;")
#define CP_WAIT0()  asm volatile("cp.async.wait_group 0;")

__device__ __forceinline__ void ldm4(uint32_t* r, uint32_t a) {
    asm volatile("ldmatrix.sync.aligned.m8n8.x4.shared.b16 {%0,%1,%2,%3}, [%4];"
                 : "=r"(r[0]), "=r"(r[1]), "=r"(r[2]), "=r"(r[3]) : "r"(a));
}
__device__ __forceinline__ void ldm4t(uint32_t* r, uint32_t a) {
    asm volatile("ldmatrix.sync.aligned.m8n8.x4.trans.shared.b16 {%0,%1,%2,%3}, [%4];"
                 : "=r"(r[0]), "=r"(r[1]), "=r"(r[2]), "=r"(r[3]) : "r"(a));
}
__device__ __forceinline__ void mma_f16(float* d, const uint32_t* a, uint32_t b0, uint32_t b1) {
    asm volatile("mma.sync.aligned.m16n8k16.row.col.f32.f16.f16.f32 "
                 "{%0,%1,%2,%3}, {%4,%5,%6,%7}, {%8,%9}, {%0,%1,%2,%3};"
                 : "+f"(d[0]), "+f"(d[1]), "+f"(d[2]), "+f"(d[3])
                 : "r"(a[0]), "r"(a[1]), "r"(a[2]), "r"(a[3]), "r"(b0), "r"(b1));
}
__device__ __forceinline__ uint32_t packh(__half a, __half b) {
    return (uint32_t)__half_as_ushort(a) | ((uint32_t)__half_as_ushort(b) << 16);
}

// ---------------------------------------------------------------------------
// K0: merged prep. blocks [0,8192): split x; [8192,8960): split wq/wkv;
// [8960,9216): fuse wo into conv.
// ---------------------------------------------------------------------------
__global__ __launch_bounds__(256) void k_prep(const float* __restrict__ x,
                                              const float* __restrict__ wq,
                                              const float* __restrict__ wkv,
                                              const float* __restrict__ wo,
                                              const float* __restrict__ bo,
                                              const float* __restrict__ wc,
                                              const float* __restrict__ bc)
{
    int b = blockIdx.x;
    if (b < 8192) {
        size_t i = (size_t)(b * 256 + threadIdx.x) * 4;
        float4 v = *(const float4*)(x + i);
        size_t o = (size_t)((i >> 12) & 255) * NPIX + ((i >> 20) << 12) + (i & 4095);
        *(uint2*)&g_xh[o] = make_uint2(packh(__float2half_rn(v.x), __float2half_rn(v.y)),
                                       packh(__float2half_rn(v.z), __float2half_rn(v.w)));
    } else if (b < 8960) {
        int i = (b - 8192) * 256 + threadIdx.x;
        int m = i >> 8, c = i & 255;
        float v = (m < 256) ? wq[m * 256 + c] * 0.125f : wkv[(m - 256) * 256 + c];
        g_wqh[i] = __float2half_rn(v);
    } else {
        int ob = (b - 8960) * 4;
        int i  = threadIdx.x;
        float a0 = 0.f, a1 = 0.f, a2 = 0.f, a3 = 0.f;
        for (int cc = 0; cc < 256; cc++) {
            float w = wo[cc * 256 + i];
            a0 += wc[(ob + 0) * 256 + cc] * w;
            a1 += wc[(ob + 1) * 256 + cc] * w;
            a2 += wc[(ob + 2) * 256 + cc] * w;
            a3 += wc[(ob + 3) * 256 + cc] * w;
        }
        float vals[4] = {a0, a1, a2, a3};
#pragma unroll
        for (int j = 0; j < 4; j++)
            g_wfh[(size_t)(ob + j) * 256 + i] = __float2half_rn(vals[j]);
        if (i < 4) {
            int o = ob + i;
            float s = 0.f;
            for (int c2 = 0; c2 < 256; c2++) s += wc[o * 256 + c2] * bo[c2];
            g_bf[o] = s + bc[o];
        }
    }
}

// ---------------------------------------------------------------------------
// K1: QKV projection. C[768,32768] = W @ X, fp16 single-term.
// k=64 stages (4 total), 3-deep cp.async.cg ring, one sync per stage.
// smem/buf: A [128][72]=18432 | B [64][136]=17408 -> 35840, x3 = 107520
// ---------------------------------------------------------------------------
#define QKA_BUF 18432
#define QK_BUF  35840
#define QK_SMEM (QK_BUF * 3)

__global__ void __launch_bounds__(256, 2) k_qkv_tc()
{
    extern __shared__ char qsm[];
    uint32_t base = smem_u32(qsm);
    int tid = threadIdx.x, lane = tid & 31, wrp = tid >> 5;
    int wm = wrp >> 1, wn = wrp & 1;
    int mt = blockIdx.y, n0 = blockIdx.x << 7;
    int m0 = mt << 7;

    float acc[2][8][4];
#pragma unroll
    for (int a = 0; a < 2; a++)
#pragma unroll
        for (int b = 0; b < 8; b++)
#pragma unroll
            for (int c = 0; c < 4; c++) acc[a][b][c] = 0.f;

    int ar = tid >> 1;                 // 128 A rows, 2 threads/row
    int abase = (tid & 1) * 4;         // 4 chunks of 8 halfs each
    int br = tid >> 2;                 // 64 B rows, 4 threads/row
    int bbase = (tid & 3) * 4;         // 4 chunks of 8 halfs each

    auto issue = [&](int s, int buf) {
        int kk = s << 6;
        uint32_t qa = base + buf * QK_BUF;
        const __half* A = g_wqh + (size_t)(m0 + ar) * 256 + kk;
#pragma unroll
        for (int j = 0; j < 4; j++) {
            int ch = abase + j;
            cp16(qa + ((ar * 72 + ch * 8) << 1), A + ch * 8);
        }
        const __half* B = g_xh + (size_t)(kk + br) * NPIX + n0;
#pragma unroll
        for (int j = 0; j < 4; j++) {
            int ch = bbase + j;
            cp16(qa + QKA_BUF + ((br * 136 + ch * 8) << 1), B + ch * 8);
        }
    };
    auto compute = [&](int buf) {
        uint32_t qa = base + buf * QK_BUF;
        uint32_t ab = qa, bb = qa + QKA_BUF;
#pragma unroll
        for (int kh = 0; kh < 64; kh += 16) {
            uint32_t ah[2][4];
#pragma unroll
            for (int mf = 0; mf < 2; mf++)
                ldm4(ah[mf], ab + (((wm * 32 + mf * 16 + (lane & 15)) * 72
                                   + kh + ((lane >> 4) << 3)) << 1));
#pragma unroll
            for (int nb = 0; nb < 4; nb++) {
                uint32_t bh4[4];
                ldm4t(bh4, bb + (((kh + ((lane >> 3) & 1) * 8 + (lane & 7)) * 136
                                  + wn * 64 + nb * 16 + ((lane >> 4) << 3)) << 1));
#pragma unroll
                for (int mf = 0; mf < 2; mf++) {
                    mma_f16(acc[mf][nb * 2],     ah[mf], bh4[0], bh4[1]);
                    mma_f16(acc[mf][nb * 2 + 1], ah[mf], bh4[2], bh4[3]);
                }
            }
        }
    };

    issue(0, 0); CP_COMMIT();
    issue(1, 1); CP_COMMIT();
#pragma unroll
    for (int s = 0; s < 4; s++) {
        if (s < 3) CP_WAIT1(); else CP_WAIT0();
        __syncthreads();
        if (s + 2 < 4) { issue(s + 2, (s + 2) % 3); CP_COMMIT(); }
        compute(s % 3);
    }
    __syncthreads();

    // epilogue: transpose per 32-row m-quarter via smem; write fp16
    float* tb = (float*)qsm;
    int g = lane >> 2, q = lane & 3;
#pragma unroll
    for (int mq = 0; mq < 4; mq++) {
        if (wm == mq) {
#pragma unroll
            for (int mf = 0; mf < 2; mf++)
#pragma unroll
                for (int nf = 0; nf < 8; nf++) {
                    int nl = wn * 64 + nf * 8 + q * 2;
                    int ml = mf * 16 + g;
                    tb[nl * 33 + ml]            = acc[mf][nf][0];
                    tb[(nl + 1) * 33 + ml]      = acc[mf][nf][1];
                    tb[nl * 33 + ml + 8]        = acc[mf][nf][2];
                    tb[(nl + 1) * 33 + ml + 8]  = acc[mf][nf][3];
                }
        }
        __syncthreads();
        int nl = tid >> 1, half2 = tid & 1;
        const float* src = tb + nl * 33 + half2 * 16;
        size_t dst = (size_t)(n0 + nl) * QKVC + m0 + mq * 32 + half2 * 16;
        unsigned short hs[16];
#pragma unroll
        for (int u = 0; u < 16; u++)
            hs[u] = __half_as_ushort(__float2half_rn(src[u]));
        *(uint4*)&g_qh[dst]     = *(uint4*)&hs[0];
        *(uint4*)&g_qh[dst + 8] = *(uint4*)&hs[8];
        __syncthreads();
    }
}

// ---------------------------------------------------------------------------
// K2: tensor-core halo attention (unchanged from R13).
// ---------------------------------------------------------------------------
#define AT_SQ    0
#define AT_SK    9216
#define AT_RELH  46080
#define AT_RELW  50688
#define AT_GW    55296
#define AT_GH    63744
#define AT_RMX   72192
#define AT_RSUM  72704
#define AT_RED2  73216
#define AT_SMEM  90624

__global__ void __launch_bounds__(256, 2) k_attn_tc(const float* __restrict__ relh,
                                                    const float* __restrict__ relw)
{
    extern __shared__ char smc[];
    uint32_t sb = smem_u32(smc);
    int t = threadIdx.x, lane = t & 31, wid = t >> 5;
    int wm = wid >> 1, wn = wid & 1;
    int nbk = blockIdx.x, hh = blockIdx.y;
    int bi = nbk >> 6, tbw = nbk & 63;
    int bh = tbw >> 3, bw = tbw & 7;
    int hco = hh * 64;

    uint32_t qB = sb + AT_SQ;
    uint32_t kB = sb + AT_SK;

    {
        int chunk = t & 7, rr = t >> 3;
        {
            int row = rr;
            int qx = row >> 3, qy = row & 7;
            size_t pix = (size_t)(bi * 4096 + (bh * 8 + qx) * 64 + bw * 8 + qy) * QKVC + hco;
            cp16(qB + ((uint32_t)(row * 9 + chunk) << 4), g_qh + pix + chunk * 8);
            row = rr + 32;
            qx = row >> 3; qy = row & 7;
            pix = (size_t)(bi * 4096 + (bh * 8 + qx) * 64 + bw * 8 + qy) * QKVC + hco;
            cp16(qB + ((uint32_t)(row * 9 + chunk) << 4), g_qh + pix + chunk * 8);
        }
#pragma unroll
        for (int p = 0; p < 8; p++) {
            int row = p * 32 + rr;
            int ki = row >> 4, kj = row & 15;
            int gh = bh * 8 - 4 + ki, gw = bw * 8 - 4 + kj;
            bool valid = ((unsigned)gh < 64u) && ((unsigned)gw < 64u);
            size_t pix = (size_t)(valid ? bi * 4096 + gh * 64 + gw : bi * 4096) * QKVC
                       + 256 + hco + chunk * 8;
            cp16z(kB + ((uint32_t)(row * 9 + chunk) << 4), g_qh + pix, valid ? 16u : 0u);
        }
        CP_COMMIT();
        for (int idx = t; idx < 1152; idx += 256) {
            ((uint32_t*)(smc + AT_RELH))[idx] = 0;
            ((uint32_t*)(smc + AT_RELW))[idx] = 0;
        }
        __syncthreads();
        for (int idx = t; idx < 1984; idx += 256) {
            int r = idx >> 6, dd = idx & 63;
            ((__half*)(smc + AT_RELH))[r * 72 + dd] = __float2half_rn(relh[idx]);
            ((__half*)(smc + AT_RELW))[r * 72 + dd] = __float2half_rn(relw[idx]);
        }
        CP_WAIT0();
    }
    __syncthreads();

    // ---- rel logits via MMA: wn==0 -> Gw, wn==1 -> Gh ----
    {
        float racc[4][4];
#pragma unroll
        for (int a = 0; a < 4; a++)
#pragma unroll
            for (int b = 0; b < 4; b++) racc[a][b] = 0.f;
        uint32_t relB = sb + (wn ? AT_RELH : AT_RELW);
#pragma unroll
        for (int kt = 0; kt < 4; kt++) {
            uint32_t ah[4];
            ldm4(ah, qB + (((wm * 16 + (lane & 15)) * 72 + kt * 16 + ((lane >> 4) << 3)) << 1));
#pragma unroll
            for (int nb = 0; nb < 2; nb++) {
                uint32_t bh4[4];
                ldm4(bh4, relB + (((nb * 16 + ((lane >> 4) << 3) + (lane & 7)) * 72
                                   + kt * 16 + (((lane >> 3) & 1) << 3)) << 1));
                mma_f16(racc[nb * 2],     ah, bh4[0], bh4[1]);
                mma_f16(racc[nb * 2 + 1], ah, bh4[2], bh4[3]);
            }
        }
        float* G = (float*)(smc + (wn ? AT_GH : AT_GW));
        int g2 = lane >> 2, tt = lane & 3;
#pragma unroll
        for (int j = 0; j < 4; j++)
#pragma unroll
            for (int e = 0; e < 4; e++) {
                int row = wm * 16 + g2 + ((e >= 2) ? 8 : 0);
                int col = j * 8 + 2 * tt + (e & 1);
                G[row * 33 + col] = racc[j][e];
            }
    }

    // ---- QK^T ----
    float s[16][4];
#pragma unroll
    for (int a = 0; a < 16; a++)
#pragma unroll
        for (int b = 0; b < 4; b++) s[a][b] = 0.f;
#pragma unroll
    for (int kt = 0; kt < 4; kt++) {
        uint32_t ah[4];
        ldm4(ah, qB + (((wm * 16 + (lane & 15)) * 72 + kt * 16 + ((lane >> 4) << 3)) << 1));
#pragma unroll
        for (int nb = 0; nb < 8; nb++) {
            uint32_t boff = (((wn * 128 + nb * 16 + ((lane >> 4) << 3) + (lane & 7)) * 72
                             + kt * 16 + (((lane >> 3) & 1) << 3)) << 1);
            uint32_t bh4[4];
            ldm4(bh4, kB + boff);
            mma_f16(s[nb * 2],     ah, bh4[0], bh4[1]);
            mma_f16(s[nb * 2 + 1], ah, bh4[2], bh4[3]);
        }
    }
    __syncthreads();

    // ---- prefetch V into K buffer ----
    {
        int chunk = t & 7, rr = t >> 3;
#pragma unroll
        for (int p = 0; p < 8; p++) {
            int row = p * 32 + rr;
            int ki = row >> 4, kj = row & 15;
            int gh = bh * 8 - 4 + ki, gw = bw * 8 - 4 + kj;
            bool valid = ((unsigned)gh < 64u) && ((unsigned)gw < 64u);
            size_t pix = (size_t)(valid ? bi * 4096 + gh * 64 + gw : bi * 4096) * QKVC
                       + 512 + hco + chunk * 8;
            cp16z(kB + ((uint32_t)(row * 9 + chunk) << 4), g_qh + pix, valid ? 16u : 0u);
        }
        CP_COMMIT();
    }

    // ---- fixup: rel logits + mask ----
    {
        const float* Gw = (const float*)(smc + AT_GW);
        const float* Gh = (const float*)(smc + AT_GH);
        int g = lane >> 2, tt = lane & 3;
#pragma unroll
        for (int nt = 0; nt < 16; nt++) {
            int jbase = wn * 128 + nt * 8 + 2 * tt;
#pragma unroll
            for (int e = 0; e < 4; e++) {
                int row = wm * 16 + g + ((e >= 2) ? 8 : 0);
                int jj = jbase + (e & 1);
                int ki = jj >> 4, kj = jj & 15;
                int gh = bh * 8 - 4 + ki, gw = bw * 8 - 4 + kj;
                if (((unsigned)gh >= 64u) || ((unsigned)gw >= 64u))
                    s[nt][e] = -3.0e38f;
                else
                    s[nt][e] += Gw[row * 33 + kj - (row & 7) + 15]
                              + Gh[row * 33 + ki - (row >> 3) + 15];
            }
        }
    }

    float* rmx  = (float*)(smc + AT_RMX);
    float* rsum = (float*)(smc + AT_RSUM);
    int gg = lane >> 2;
    int rA = wm * 16 + gg, rB = rA + 8;
    {
        float mA = -3.4e38f, mB = -3.4e38f;
#pragma unroll
        for (int nt = 0; nt < 16; nt++) {
            mA = fmaxf(mA, fmaxf(s[nt][0], s[nt][1]));
            mB = fmaxf(mB, fmaxf(s[nt][2], s[nt][3]));
        }
        mA = fmaxf(mA, __shfl_xor_sync(0xffffffffu, mA, 1));
        mA = fmaxf(mA, __shfl_xor_sync(0xffffffffu, mA, 2));
        mB = fmaxf(mB, __shfl_xor_sync(0xffffffffu, mB, 1));
        mB = fmaxf(mB, __shfl_xor_sync(0xffffffffu, mB, 2));
        if ((lane & 3) == 0) { rmx[wn * 64 + rA] = mA; rmx[wn * 64 + rB] = mB; }
    }
    __syncthreads();
    {
        float mA = fmaxf(rmx[rA], rmx[64 + rA]);
        float mB = fmaxf(rmx[rB], rmx[64 + rB]);
        float sA = 0.f, sB = 0.f;
#pragma unroll
        for (int nt = 0; nt < 16; nt++) {
            s[nt][0] = __expf(s[nt][0] - mA); sA += s[nt][0];
            s[nt][1] = __expf(s[nt][1] - mA); sA += s[nt][1];
            s[nt][2] = __expf(s[nt][2] - mB); sB += s[nt][2];
            s[nt][3] = __expf(s[nt][3] - mB); sB += s[nt][3];
        }
        sA += __shfl_xor_sync(0xffffffffu, sA, 1);
        sA += __shfl_xor_sync(0xffffffffu, sA, 2);
        sB += __shfl_xor_sync(0xffffffffu, sB, 1);
        sB += __shfl_xor_sync(0xffffffffu, sB, 2);
        if ((lane & 3) == 0) { rsum[wn * 64 + rA] = sA; rsum[wn * 64 + rB] = sB; }
    }
    __syncthreads();
    {
        float invA = 1.0f / (rsum[rA] + rsum[64 + rA]);
        float invB = 1.0f / (rsum[rB] + rsum[64 + rB]);
#pragma unroll
        for (int nt = 0; nt < 16; nt++) {
            __half h0 = __float2half_rn(s[nt][0] * invA);
            __half h1 = __float2half_rn(s[nt][1] * invA);
            __half h2 = __float2half_rn(s[nt][2] * invB);
            __half h3 = __float2half_rn(s[nt][3] * invB);
            s[nt][0] = __uint_as_float(packh(h0, h1));
            s[nt][1] = __uint_as_float(packh(h2, h3));
        }
    }
    CP_WAIT0();
    __syncthreads();

    // ---- AV ----
    float avc[8][4];
#pragma unroll
    for (int a = 0; a < 8; a++)
#pragma unroll
        for (int b = 0; b < 4; b++) avc[a][b] = 0.f;
#pragma unroll
    for (int kt2 = 0; kt2 < 8; kt2++) {
        uint32_t pa[4] = { __float_as_uint(s[2 * kt2][0]), __float_as_uint(s[2 * kt2][1]),
                           __float_as_uint(s[2 * kt2 + 1][0]), __float_as_uint(s[2 * kt2 + 1][1]) };
#pragma unroll
        for (int nb = 0; nb < 4; nb++) {
            uint32_t off = (((wn * 128 + kt2 * 16 + ((lane >> 3) & 1) * 8 + (lane & 7)) * 72
                            + nb * 16 + ((lane >> 4) << 3)) << 1);
            uint32_t vh4[4];
            ldm4t(vh4, kB + off);
            mma_f16(avc[nb * 2],     pa, vh4[0], vh4[1]);
            mma_f16(avc[nb * 2 + 1], pa, vh4[2], vh4[3]);
        }
    }

    // dual-buffer reduction
    float* Red1 = (float*)(smc + AT_SK);
    float* Red2 = (float*)(smc + AT_RED2);
    __syncthreads();
    {
        float* Rd = wn ? Red2 : Red1;
#pragma unroll
        for (int nf = 0; nf < 8; nf++)
#pragma unroll
            for (int e = 0; e < 4; e++) {
                int row = wm * 16 + gg + ((e >= 2) ? 8 : 0);
                int col = nf * 8 + 2 * (lane & 3) + (e & 1);
                Rd[row * 68 + col] = avc[nf][e];
            }
    }
    __syncthreads();

    {
        int qi = t >> 2, c0 = (t & 3) * 16;
        int qx = qi >> 3, qy = qi & 7;
        size_t base = (size_t)(bi * 4096 + (bh * 8 + qx) * 64 + bw * 8 + qy) * 256 + hco + c0;
        unsigned short hs[16];
#pragma unroll
        for (int u = 0; u < 16; u++)
            hs[u] = __half_as_ushort(__float2half_rn(Red1[qi * 68 + c0 + u]
                                                   + Red2[qi * 68 + c0 + u]));
        *(uint4*)&g_bh[base]     = *(uint4*)&hs[0];
        *(uint4*)&g_bh[base + 8] = *(uint4*)&hs[8];
    }
}

// ---------------------------------------------------------------------------
// K3: output GEMM + PixelShuffle. k=64 stages (4), 3-deep cg ring.
// smem/buf: A [128][72]=18432 | B [128][72]=18432 -> 36864, x3 = 110592
// ---------------------------------------------------------------------------
#define KOA_BUF 18432
#define KO_BUF  36864
#define KO_SMEM (KO_BUF * 3)

__global__ void __launch_bounds__(256, 2) k_out_tc(float* __restrict__ out)
{
    extern __shared__ char osm[];
    uint32_t base = smem_u32(osm);
    int tid = threadIdx.x, lane = tid & 31, wrp = tid >> 5;
    int wm = wrp >> 1, wn = wrp & 1;
    int mt = blockIdx.y, n0 = blockIdx.x << 7;
    int m0 = mt << 7;

    float acc[2][8][4];
#pragma unroll
    for (int a = 0; a < 2; a++)
#pragma unroll
        for (int b = 0; b < 8; b++)
#pragma unroll
            for (int c = 0; c < 4; c++) acc[a][b][c] = 0.f;

    int ar = tid >> 1;
    int abase = (tid & 1) * 4;

    auto issue = [&](int s, int buf) {
        int kk = s << 6;
        uint32_t qa = base + buf * KO_BUF;
        const __half* A = g_wfh + (size_t)(m0 + ar) * 256 + kk;
#pragma unroll
        for (int j = 0; j < 4; j++) {
            int ch = abase + j;
            cp16(qa + ((ar * 72 + ch * 8) << 1), A + ch * 8);
        }
        const __half* B = g_bh + (size_t)(n0 + ar) * 256 + kk;
#pragma unroll
        for (int j = 0; j < 4; j++) {
            int ch = abase + j;
            cp16(qa + KOA_BUF + ((ar * 72 + ch * 8) << 1), B + ch * 8);
        }
    };
    auto compute = [&](int buf) {
        uint32_t qa = base + buf * KO_BUF;
        uint32_t ab = qa, bb = qa + KOA_BUF;
#pragma unroll
        for (int kh = 0; kh < 64; kh += 16) {
            uint32_t ah[2][4];
#pragma unroll
            for (int mf = 0; mf < 2; mf++)
                ldm4(ah[mf], ab + (((wm * 32 + mf * 16 + (lane & 15)) * 72
                                   + kh + ((lane >> 4) << 3)) << 1));
#pragma unroll
            for (int nb = 0; nb < 4; nb++) {
                uint32_t bh4[4];
                ldm4(bh4, bb + (((wn * 64 + nb * 16 + ((lane >> 4) << 3) + (lane & 7)) * 72
                                 + kh + (((lane >> 3) & 1) << 3)) << 1));
#pragma unroll
                for (int mf = 0; mf < 2; mf++) {
                    mma_f16(acc[mf][nb * 2],     ah[mf], bh4[0], bh4[1]);
                    mma_f16(acc[mf][nb * 2 + 1], ah[mf], bh4[2], bh4[3]);
                }
            }
        }
    };

    issue(0, 0); CP_COMMIT();
    issue(1, 1); CP_COMMIT();
#pragma unroll
    for (int s = 0; s < 4; s++) {
        if (s < 3) CP_WAIT1(); else CP_WAIT0();
        __syncthreads();
        if (s + 2 < 4) { issue(s + 2, (s + 2) % 3); CP_COMMIT(); }
        compute(s % 3);
    }

    int g = lane >> 2, q = lane & 3;
    int h0 = (n0 & 4095) >> 6, bimg = n0 >> 12;
    int hrow = h0 + wn;
#pragma unroll
    for (int mf = 0; mf < 2; mf++) {
#pragma unroll
        for (int which = 0; which < 2; which++) {
            int mm = m0 + wm * 32 + mf * 16 + g + which * 8;
            float bias = g_bf[mm];
            int cch = mm >> 2, r = (mm >> 1) & 1, s2 = mm & 1;
            float* rowp = out + ((size_t)(bimg * 256 + cch) * 128 + 2 * hrow + r) * 128 + s2;
#pragma unroll
            for (int nf = 0; nf < 8; nf++) {
                int w0 = nf * 8 + 2 * q;
                rowp[2 * w0]     = acc[mf][nf][which * 2 + 0] + bias;
                rowp[2 * w0 + 2] = acc[mf][nf][which * 2 + 1] + bias;
            }
        }
    }
}

// ---------------------------------------------------------------------------
extern "C" void kernel_launch(void* const* d_in, const int* in_sizes, int n_in,
                              void* d_out, int out_size)
{
    const float* x    = (const float*)d_in[0];
    const float* wq   = (const float*)d_in[1];
    const float* wkv  = (const float*)d_in[2];
    const float* wo   = (const float*)d_in[3];
    const float* bo   = (const float*)d_in[4];
    const float* relh = (const float*)d_in[5];
    const float* relw = (const float*)d_in[6];
    const float* wc   = (const float*)d_in[7];
    const float* bc   = (const float*)d_in[8];
    float* out = (float*)d_out;

    cudaFuncSetAttribute(k_qkv_tc,  cudaFuncAttributeMaxDynamicSharedMemorySize, QK_SMEM);
    cudaFuncSetAttribute(k_attn_tc, cudaFuncAttributeMaxDynamicSharedMemorySize, AT_SMEM);
    cudaFuncSetAttribute(k_out_tc,  cudaFuncAttributeMaxDynamicSharedMemorySize, KO_SMEM);

    k_prep<<<9216, 256>>>(x, wq, wkv, wo, bo, wc, bc);
    k_qkv_tc<<<dim3(256, 6), 256, QK_SMEM>>>();
    k_attn_tc<<<dim3(512, 4), 256, AT_SMEM>>>(relh, relw);
    k_out_tc<<<dim3(256, 8), 256, KO_SMEM>>>(out);
}

// round 15
// speedup vs baseline: 1.0558x; 1.0558x over previous
#include <cuda_runtime.h>
#include <cuda_fp16.h>
#include <stdint.h>

#define NPIX 32768            // B*H*W
#define QKVC 768

// Scratch (device globals; 16B-aligned)
__device__ __align__(16) __half g_qh[NPIX * QKVC];  // qkv fp16, [pixel][q|k|v]
__device__ __align__(16) __half g_bh[NPIX * 256];   // attn out fp16, [n][256]
__device__ __align__(16) __half g_wfh[1024 * 256];  // fused conv W fp16, [m][k]
__device__ __align__(16) __half g_wqh[QKVC * 256];  // qkv W fp16 (q pre-scaled), [m][k]
__device__ __align__(16) __half g_xh[256 * NPIX];   // x fp16, [k][n]
__device__ float g_bf[1024];

// ---------------------------------------------------------------------------
// helpers (non-arch-specific PTX only: cp.async / ldmatrix / mma.sync)
// ---------------------------------------------------------------------------
__device__ __forceinline__ uint32_t smem_u32(const void* p) {
    uint32_t a;
    asm("{ .reg .u64 t; cvta.to.shared.u64 t, %1; cvt.u32.u64 %0, t; }" : "=r"(a) : "l"(p));
    return a;
}
__device__ __forceinline__ void cp16(uint32_t d, const void* s) {
    asm volatile("cp.async.cg.shared.global [%0], [%1], 16;" :: "r"(d), "l"(s));
}
__device__ __forceinline__ void cp16z(uint32_t d, const void* s, uint32_t sz) {
    asm volatile("cp.async.cg.shared.global [%0], [%1], 16, %2;" :: "r"(d), "l"(s), "r"(sz));
}
#define CP_COMMIT() asm volatile("cp.async.commit_group;")
#define CP_WAIT2()  asm volatile("cp.async.wait_group 2;")
#define CP_WAIT1()  asm volatile("cp.async.wait_group 1;")
#define CP_WAIT0()  asm volatile("cp.async.wait_group 0;")

__device__ __forceinline__ void ldm4(uint32_t* r, uint32_t a) {
    asm volatile("ldmatrix.sync.aligned.m8n8.x4.shared.b16 {%0,%1,%2,%3}, [%4];"
                 : "=r"(r[0]), "=r"(r[1]), "=r"(r[2]), "=r"(r[3]) : "r"(a));
}
__device__ __forceinline__ void ldm4t(uint32_t* r, uint32_t a) {
    asm volatile("ldmatrix.sync.aligned.m8n8.x4.trans.shared.b16 {%0,%1,%2,%3}, [%4];"
                 : "=r"(r[0]), "=r"(r[1]), "=r"(r[2]), "=r"(r[3]) : "r"(a));
}
__device__ __forceinline__ void mma_f16(float* d, const uint32_t* a, uint32_t b0, uint32_t b1) {
    asm volatile("mma.sync.aligned.m16n8k16.row.col.f32.f16.f16.f32 "
                 "{%0,%1,%2,%3}, {%4,%5,%6,%7}, {%8,%9}, {%0,%1,%2,%3};"
                 : "+f"(d[0]), "+f"(d[1]), "+f"(d[2]), "+f"(d[3])
                 : "r"(a[0]), "r"(a[1]), "r"(a[2]), "r"(a[3]), "r"(b0), "r"(b1));
}
__device__ __forceinline__ uint32_t packh(__half a, __half b) {
    return (uint32_t)__half_as_ushort(a) | ((uint32_t)__half_as_ushort(b) << 16);
}

// ---------------------------------------------------------------------------
// K0: merged prep. blocks [0,8192): split x; [8192,8960): split wq/wkv;
// [8960,9216): fuse wo into conv.
// ---------------------------------------------------------------------------
__global__ __launch_bounds__(256) void k_prep(const float* __restrict__ x,
                                              const float* __restrict__ wq,
                                              const float* __restrict__ wkv,
                                              const float* __restrict__ wo,
                                              const float* __restrict__ bo,
                                              const float* __restrict__ wc,
                                              const float* __restrict__ bc)
{
    int b = blockIdx.x;
    if (b < 8192) {
        size_t i = (size_t)(b * 256 + threadIdx.x) * 4;
        float4 v = *(const float4*)(x + i);
        size_t o = (size_t)((i >> 12) & 255) * NPIX + ((i >> 20) << 12) + (i & 4095);
        *(uint2*)&g_xh[o] = make_uint2(packh(__float2half_rn(v.x), __float2half_rn(v.y)),
                                       packh(__float2half_rn(v.z), __float2half_rn(v.w)));
    } else if (b < 8960) {
        int i = (b - 8192) * 256 + threadIdx.x;
        int m = i >> 8, c = i & 255;
        float v = (m < 256) ? wq[m * 256 + c] * 0.125f : wkv[(m - 256) * 256 + c];
        g_wqh[i] = __float2half_rn(v);
    } else {
        int ob = (b - 8960) * 4;
        int i  = threadIdx.x;
        float a0 = 0.f, a1 = 0.f, a2 = 0.f, a3 = 0.f;
        for (int cc = 0; cc < 256; cc++) {
            float w = wo[cc * 256 + i];
            a0 += wc[(ob + 0) * 256 + cc] * w;
            a1 += wc[(ob + 1) * 256 + cc] * w;
            a2 += wc[(ob + 2) * 256 + cc] * w;
            a3 += wc[(ob + 3) * 256 + cc] * w;
        }
        float vals[4] = {a0, a1, a2, a3};
#pragma unroll
        for (int j = 0; j < 4; j++)
            g_wfh[(size_t)(ob + j) * 256 + i] = __float2half_rn(vals[j]);
        if (i < 4) {
            int o = ob + i;
            float s = 0.f;
            for (int c2 = 0; c2 < 256; c2++) s += wc[o * 256 + c2] * bo[c2];
            g_bf[o] = s + bc[o];
        }
    }
}

// ---------------------------------------------------------------------------
// K1: QKV projection. C[768,32768] = W @ X, fp16 single-term.
// k=32 stages (8 total), 4-stage cp.async.cg ring, fully unrolled. (R13.)
// ---------------------------------------------------------------------------
#define QK_BUF  18944
#define QK_SMEM (QK_BUF * 4)

__global__ void __launch_bounds__(256, 2) k_qkv_tc()
{
    extern __shared__ char qsm[];
    uint32_t base = smem_u32(qsm);
    int tid = threadIdx.x, lane = tid & 31, wrp = tid >> 5;
    int wm = wrp >> 1, wn = wrp & 1;
    int mt = blockIdx.y, n0 = blockIdx.x << 7;
    int m0 = mt << 7;

    float acc[2][8][4];
#pragma unroll
    for (int a = 0; a < 2; a++)
#pragma unroll
        for (int b = 0; b < 8; b++)
#pragma unroll
            for (int c = 0; c < 4; c++) acc[a][b][c] = 0.f;

    int ar = tid >> 1, ac = (tid & 1) << 4;
    int br = tid >> 3, bc = (tid & 7) << 4;

    auto issue = [&](int s, int buf) {
        int kk = s << 5;
        uint32_t qa = base + buf * QK_BUF;
        const __half* A = g_wqh + (size_t)(m0 + ar) * 256 + kk + ac;
        uint32_t da = qa + ((ar * 40 + ac) << 1);
        cp16(da, A); cp16(da + 16, A + 8);
        const __half* B = g_xh + (size_t)(kk + br) * NPIX + n0 + bc;
        uint32_t db = qa + 10240 + ((br * 136 + bc) << 1);
        cp16(db, B); cp16(db + 16, B + 8);
    };
    auto compute = [&](int buf) {
        uint32_t qa = base + buf * QK_BUF;
        uint32_t ab = qa, bb = qa + 10240;
#pragma unroll
        for (int kh = 0; kh < 32; kh += 16) {
            uint32_t ah[2][4];
#pragma unroll
            for (int mf = 0; mf < 2; mf++)
                ldm4(ah[mf], ab + (((wm * 32 + mf * 16 + (lane & 15)) * 40
                                   + kh + ((lane >> 4) << 3)) << 1));
#pragma unroll
            for (int nb = 0; nb < 4; nb++) {
                uint32_t bh4[4];
                ldm4t(bh4, bb + (((kh + ((lane >> 3) & 1) * 8 + (lane & 7)) * 136
                                  + wn * 64 + nb * 16 + ((lane >> 4) << 3)) << 1));
#pragma unroll
                for (int mf = 0; mf < 2; mf++) {
                    mma_f16(acc[mf][nb * 2],     ah[mf], bh4[0], bh4[1]);
                    mma_f16(acc[mf][nb * 2 + 1], ah[mf], bh4[2], bh4[3]);
                }
            }
        }
    };

    issue(0, 0); CP_COMMIT();
    issue(1, 1); CP_COMMIT();
    issue(2, 2); CP_COMMIT();
#pragma unroll
    for (int s = 0; s < 8; s++) {
        if (s < 6) CP_WAIT2();
        else if (s == 6) CP_WAIT1();
        else CP_WAIT0();
        __syncthreads();
        if (s + 3 < 8) { issue(s + 3, (s + 3) & 3); CP_COMMIT(); }
        compute(s & 3);
    }
    __syncthreads();

    // epilogue: transpose per 32-row m-quarter via smem; write fp16
    float* tb = (float*)qsm;
    int g = lane >> 2, q = lane & 3;
#pragma unroll
    for (int mq = 0; mq < 4; mq++) {
        if (wm == mq) {
#pragma unroll
            for (int mf = 0; mf < 2; mf++)
#pragma unroll
                for (int nf = 0; nf < 8; nf++) {
                    int nl = wn * 64 + nf * 8 + q * 2;
                    int ml = mf * 16 + g;
                    tb[nl * 33 + ml]            = acc[mf][nf][0];
                    tb[(nl + 1) * 33 + ml]      = acc[mf][nf][1];
                    tb[nl * 33 + ml + 8]        = acc[mf][nf][2];
                    tb[(nl + 1) * 33 + ml + 8]  = acc[mf][nf][3];
                }
        }
        __syncthreads();
        int nl = tid >> 1, half2 = tid & 1;
        const float* src = tb + nl * 33 + half2 * 16;
        size_t dst = (size_t)(n0 + nl) * QKVC + m0 + mq * 32 + half2 * 16;
        unsigned short hs[16];
#pragma unroll
        for (int u = 0; u < 16; u++)
            hs[u] = __half_as_ushort(__float2half_rn(src[u]));
        *(uint4*)&g_qh[dst]     = *(uint4*)&hs[0];
        *(uint4*)&g_qh[dst + 8] = *(uint4*)&hs[8];
        __syncthreads();
    }
}

// ---------------------------------------------------------------------------
// K2: tensor-core halo attention (R13 version, unchanged).
// ---------------------------------------------------------------------------
#define AT_SQ    0
#define AT_SK    9216
#define AT_RELH  46080
#define AT_RELW  50688
#define AT_GW    55296
#define AT_GH    63744
#define AT_RMX   72192
#define AT_RSUM  72704
#define AT_RED2  73216
#define AT_SMEM  90624

__global__ void __launch_bounds__(256, 2) k_attn_tc(const float* __restrict__ relh,
                                                    const float* __restrict__ relw)
{
    extern __shared__ char smc[];
    uint32_t sb = smem_u32(smc);
    int t = threadIdx.x, lane = t & 31, wid = t >> 5;
    int wm = wid >> 1, wn = wid & 1;
    int nbk = blockIdx.x, hh = blockIdx.y;
    int bi = nbk >> 6, tbw = nbk & 63;
    int bh = tbw >> 3, bw = tbw & 7;
    int hco = hh * 64;

    uint32_t qB = sb + AT_SQ;
    uint32_t kB = sb + AT_SK;

    {
        int chunk = t & 7, rr = t >> 3;
        {
            int row = rr;
            int qx = row >> 3, qy = row & 7;
            size_t pix = (size_t)(bi * 4096 + (bh * 8 + qx) * 64 + bw * 8 + qy) * QKVC + hco;
            cp16(qB + ((uint32_t)(row * 9 + chunk) << 4), g_qh + pix + chunk * 8);
            row = rr + 32;
            qx = row >> 3; qy = row & 7;
            pix = (size_t)(bi * 4096 + (bh * 8 + qx) * 64 + bw * 8 + qy) * QKVC + hco;
            cp16(qB + ((uint32_t)(row * 9 + chunk) << 4), g_qh + pix + chunk * 8);
        }
#pragma unroll
        for (int p = 0; p < 8; p++) {
            int row = p * 32 + rr;
            int ki = row >> 4, kj = row & 15;
            int gh = bh * 8 - 4 + ki, gw = bw * 8 - 4 + kj;
            bool valid = ((unsigned)gh < 64u) && ((unsigned)gw < 64u);
            size_t pix = (size_t)(valid ? bi * 4096 + gh * 64 + gw : bi * 4096) * QKVC
                       + 256 + hco + chunk * 8;
            cp16z(kB + ((uint32_t)(row * 9 + chunk) << 4), g_qh + pix, valid ? 16u : 0u);
        }
        CP_COMMIT();
        for (int idx = t; idx < 1152; idx += 256) {
            ((uint32_t*)(smc + AT_RELH))[idx] = 0;
            ((uint32_t*)(smc + AT_RELW))[idx] = 0;
        }
        __syncthreads();
        for (int idx = t; idx < 1984; idx += 256) {
            int r = idx >> 6, dd = idx & 63;
            ((__half*)(smc + AT_RELH))[r * 72 + dd] = __float2half_rn(relh[idx]);
            ((__half*)(smc + AT_RELW))[r * 72 + dd] = __float2half_rn(relw[idx]);
        }
        CP_WAIT0();
    }
    __syncthreads();

    // ---- rel logits via MMA: wn==0 -> Gw, wn==1 -> Gh ----
    {
        float racc[4][4];
#pragma unroll
        for (int a = 0; a < 4; a++)
#pragma unroll
            for (int b = 0; b < 4; b++) racc[a][b] = 0.f;
        uint32_t relB = sb + (wn ? AT_RELH : AT_RELW);
#pragma unroll
        for (int kt = 0; kt < 4; kt++) {
            uint32_t ah[4];
            ldm4(ah, qB + (((wm * 16 + (lane & 15)) * 72 + kt * 16 + ((lane >> 4) << 3)) << 1));
#pragma unroll
            for (int nb = 0; nb < 2; nb++) {
                uint32_t bh4[4];
                ldm4(bh4, relB + (((nb * 16 + ((lane >> 4) << 3) + (lane & 7)) * 72
                                   + kt * 16 + (((lane >> 3) & 1) << 3)) << 1));
                mma_f16(racc[nb * 2],     ah, bh4[0], bh4[1]);
                mma_f16(racc[nb * 2 + 1], ah, bh4[2], bh4[3]);
            }
        }
        float* G = (float*)(smc + (wn ? AT_GH : AT_GW));
        int g2 = lane >> 2, tt = lane & 3;
#pragma unroll
        for (int j = 0; j < 4; j++)
#pragma unroll
            for (int e = 0; e < 4; e++) {
                int row = wm * 16 + g2 + ((e >= 2) ? 8 : 0);
                int col = j * 8 + 2 * tt + (e & 1);
                G[row * 33 + col] = racc[j][e];
            }
    }

    // ---- QK^T ----
    float s[16][4];
#pragma unroll
    for (int a = 0; a < 16; a++)
#pragma unroll
        for (int b = 0; b < 4; b++) s[a][b] = 0.f;
#pragma unroll
    for (int kt = 0; kt < 4; kt++) {
        uint32_t ah[4];
        ldm4(ah, qB + (((wm * 16 + (lane & 15)) * 72 + kt * 16 + ((lane >> 4) << 3)) << 1));
#pragma unroll
        for (int nb = 0; nb < 8; nb++) {
            uint32_t boff = (((wn * 128 + nb * 16 + ((lane >> 4) << 3) + (lane & 7)) * 72
                             + kt * 16 + (((lane >> 3) & 1) << 3)) << 1);
            uint32_t bh4[4];
            ldm4(bh4, kB + boff);
            mma_f16(s[nb * 2],     ah, bh4[0], bh4[1]);
            mma_f16(s[nb * 2 + 1], ah, bh4[2], bh4[3]);
        }
    }
    __syncthreads();

    // ---- prefetch V into K buffer ----
    {
        int chunk = t & 7, rr = t >> 3;
#pragma unroll
        for (int p = 0; p < 8; p++) {
            int row = p * 32 + rr;
            int ki = row >> 4, kj = row & 15;
            int gh = bh * 8 - 4 + ki, gw = bw * 8 - 4 + kj;
            bool valid = ((unsigned)gh < 64u) && ((unsigned)gw < 64u);
            size_t pix = (size_t)(valid ? bi * 4096 + gh * 64 + gw : bi * 4096) * QKVC
                       + 512 + hco + chunk * 8;
            cp16z(kB + ((uint32_t)(row * 9 + chunk) << 4), g_qh + pix, valid ? 16u : 0u);
        }
        CP_COMMIT();
    }

    // ---- fixup: rel logits + mask ----
    {
        const float* Gw = (const float*)(smc + AT_GW);
        const float* Gh = (const float*)(smc + AT_GH);
        int g = lane >> 2, tt = lane & 3;
#pragma unroll
        for (int nt = 0; nt < 16; nt++) {
            int jbase = wn * 128 + nt * 8 + 2 * tt;
#pragma unroll
            for (int e = 0; e < 4; e++) {
                int row = wm * 16 + g + ((e >= 2) ? 8 : 0);
                int jj = jbase + (e & 1);
                int ki = jj >> 4, kj = jj & 15;
                int gh = bh * 8 - 4 + ki, gw = bw * 8 - 4 + kj;
                if (((unsigned)gh >= 64u) || ((unsigned)gw >= 64u))
                    s[nt][e] = -3.0e38f;
                else
                    s[nt][e] += Gw[row * 33 + kj - (row & 7) + 15]
                              + Gh[row * 33 + ki - (row >> 3) + 15];
            }
        }
    }

    float* rmx  = (float*)(smc + AT_RMX);
    float* rsum = (float*)(smc + AT_RSUM);
    int gg = lane >> 2;
    int rA = wm * 16 + gg, rB = rA + 8;
    {
        float mA = -3.4e38f, mB = -3.4e38f;
#pragma unroll
        for (int nt = 0; nt < 16; nt++) {
            mA = fmaxf(mA, fmaxf(s[nt][0], s[nt][1]));
            mB = fmaxf(mB, fmaxf(s[nt][2], s[nt][3]));
        }
        mA = fmaxf(mA, __shfl_xor_sync(0xffffffffu, mA, 1));
        mA = fmaxf(mA, __shfl_xor_sync(0xffffffffu, mA, 2));
        mB = fmaxf(mB, __shfl_xor_sync(0xffffffffu, mB, 1));
        mB = fmaxf(mB, __shfl_xor_sync(0xffffffffu, mB, 2));
        if ((lane & 3) == 0) { rmx[wn * 64 + rA] = mA; rmx[wn * 64 + rB] = mB; }
    }
    __syncthreads();
    {
        float mA = fmaxf(rmx[rA], rmx[64 + rA]);
        float mB = fmaxf(rmx[rB], rmx[64 + rB]);
        float sA = 0.f, sB = 0.f;
#pragma unroll
        for (int nt = 0; nt < 16; nt++) {
            s[nt][0] = __expf(s[nt][0] - mA); sA += s[nt][0];
            s[nt][1] = __expf(s[nt][1] - mA); sA += s[nt][1];
            s[nt][2] = __expf(s[nt][2] - mB); sB += s[nt][2];
            s[nt][3] = __expf(s[nt][3] - mB); sB += s[nt][3];
        }
        sA += __shfl_xor_sync(0xffffffffu, sA, 1);
        sA += __shfl_xor_sync(0xffffffffu, sA, 2);
        sB += __shfl_xor_sync(0xffffffffu, sB, 1);
        sB += __shfl_xor_sync(0xffffffffu, sB, 2);
        if ((lane & 3) == 0) { rsum[wn * 64 + rA] = sA; rsum[wn * 64 + rB] = sB; }
    }
    __syncthreads();
    {
        float invA = 1.0f / (rsum[rA] + rsum[64 + rA]);
        float invB = 1.0f / (rsum[rB] + rsum[64 + rB]);
#pragma unroll
        for (int nt = 0; nt < 16; nt++) {
            __half h0 = __float2half_rn(s[nt][0] * invA);
            __half h1 = __float2half_rn(s[nt][1] * invA);
            __half h2 = __float2half_rn(s[nt][2] * invB);
            __half h3 = __float2half_rn(s[nt][3] * invB);
            s[nt][0] = __uint_as_float(packh(h0, h1));
            s[nt][1] = __uint_as_float(packh(h2, h3));
        }
    }
    CP_WAIT0();
    __syncthreads();

    // ---- AV ----
    float avc[8][4];
#pragma unroll
    for (int a = 0; a < 8; a++)
#pragma unroll
        for (int b = 0; b < 4; b++) avc[a][b] = 0.f;
#pragma unroll
    for (int kt2 = 0; kt2 < 8; kt2++) {
        uint32_t pa[4] = { __float_as_uint(s[2 * kt2][0]), __float_as_uint(s[2 * kt2][1]),
                           __float_as_uint(s[2 * kt2 + 1][0]), __float_as_uint(s[2 * kt2 + 1][1]) };
#pragma unroll
        for (int nb = 0; nb < 4; nb++) {
            uint32_t off = (((wn * 128 + kt2 * 16 + ((lane >> 3) & 1) * 8 + (lane & 7)) * 72
                            + nb * 16 + ((lane >> 4) << 3)) << 1);
            uint32_t vh4[4];
            ldm4t(vh4, kB + off);
            mma_f16(avc[nb * 2],     pa, vh4[0], vh4[1]);
            mma_f16(avc[nb * 2 + 1], pa, vh4[2], vh4[3]);
        }
    }

    // dual-buffer reduction: wn==0 -> Red1 (overlays sK), wn==1 -> Red2
    float* Red1 = (float*)(smc + AT_SK);
    float* Red2 = (float*)(smc + AT_RED2);
    __syncthreads();
    {
        float* Rd = wn ? Red2 : Red1;
#pragma unroll
        for (int nf = 0; nf < 8; nf++)
#pragma unroll
            for (int e = 0; e < 4; e++) {
                int row = wm * 16 + gg + ((e >= 2) ? 8 : 0);
                int col = nf * 8 + 2 * (lane & 3) + (e & 1);
                Rd[row * 68 + col] = avc[nf][e];
            }
    }
    __syncthreads();

    {
        int qi = t >> 2, c0 = (t & 3) * 16;
        int qx = qi >> 3, qy = qi & 7;
        size_t base = (size_t)(bi * 4096 + (bh * 8 + qx) * 64 + bw * 8 + qy) * 256 + hco + c0;
        unsigned short hs[16];
#pragma unroll
        for (int u = 0; u < 16; u++)
            hs[u] = __half_as_ushort(__float2half_rn(Red1[qi * 68 + c0 + u]
                                                   + Red2[qi * 68 + c0 + u]));
        *(uint4*)&g_bh[base]     = *(uint4*)&hs[0];
        *(uint4*)&g_bh[base + 8] = *(uint4*)&hs[8];
    }
}

// ---------------------------------------------------------------------------
// K3: output GEMM + PixelShuffle. k=32 stages, 4-stage cg ring, unrolled. (R13.)
// ---------------------------------------------------------------------------
#define KO_BUF  20480
#define KO_SMEM (KO_BUF * 4)

__global__ void __launch_bounds__(256, 2) k_out_tc(float* __restrict__ out)
{
    extern __shared__ char osm[];
    uint32_t base = smem_u32(osm);
    int tid = threadIdx.x, lane = tid & 31, wrp = tid >> 5;
    int wm = wrp >> 1, wn = wrp & 1;
    int mt = blockIdx.y, n0 = blockIdx.x << 7;
    int m0 = mt << 7;

    float acc[2][8][4];
#pragma unroll
    for (int a = 0; a < 2; a++)
#pragma unroll
        for (int b = 0; b < 8; b++)
#pragma unroll
            for (int c = 0; c < 4; c++) acc[a][b][c] = 0.f;

    int ar = tid >> 1, ac = (tid & 1) << 4;

    auto issue = [&](int s, int buf) {
        int kk = s << 5;
        uint32_t qa = base + buf * KO_BUF;
        const __half* A = g_wfh + (size_t)(m0 + ar) * 256 + kk + ac;
        uint32_t da = qa + ((ar * 40 + ac) << 1);
        cp16(da, A); cp16(da + 16, A + 8);
        const __half* B = g_bh + (size_t)(n0 + ar) * 256 + kk + ac;
        uint32_t db = qa + 10240 + ((ar * 40 + ac) << 1);
        cp16(db, B); cp16(db + 16, B + 8);
    };
    auto compute = [&](int buf) {
        uint32_t qa = base + buf * KO_BUF;
        uint32_t ab = qa, bb = qa + 10240;
#pragma unroll
        for (int kh = 0; kh < 32; kh += 16) {
            uint32_t ah[2][4];
#pragma unroll
            for (int mf = 0; mf < 2; mf++)
                ldm4(ah[mf], ab + (((wm * 32 + mf * 16 + (lane & 15)) * 40
                                   + kh + ((lane >> 4) << 3)) << 1));
#pragma unroll
            for (int nb = 0; nb < 4; nb++) {
                uint32_t bh4[4];
                ldm4(bh4, bb + (((wn * 64 + nb * 16 + ((lane >> 4) << 3) + (lane & 7)) * 40
                                 + kh + (((lane >> 3) & 1) << 3)) << 1));
#pragma unroll
                for (int mf = 0; mf < 2; mf++) {
                    mma_f16(acc[mf][nb * 2],     ah[mf], bh4[0], bh4[1]);
                    mma_f16(acc[mf][nb * 2 + 1], ah[mf], bh4[2], bh4[3]);
                }
            }
        }
    };

    issue(0, 0); CP_COMMIT();
    issue(1, 1); CP_COMMIT();
    issue(2, 2); CP_COMMIT();
#pragma unroll
    for (int s = 0; s < 8; s++) {
        if (s < 6) CP_WAIT2();
        else if (s == 6) CP_WAIT1();
        else CP_WAIT0();
        __syncthreads();
        if (s + 3 < 8) { issue(s + 3, (s + 3) & 3); CP_COMMIT(); }
        compute(s & 3);
    }

    int g = lane >> 2, q = lane & 3;
    int h0 = (n0 & 4095) >> 6, bimg = n0 >> 12;
    int hrow = h0 + wn;
#pragma unroll
    for (int mf = 0; mf < 2; mf++) {
#pragma unroll
        for (int which = 0; which < 2; which++) {
            int mm = m0 + wm * 32 + mf * 16 + g + which * 8;
            float bias = g_bf[mm];
            int cch = mm >> 2, r = (mm >> 1) & 1, s2 = mm & 1;
            float* rowp = out + ((size_t)(bimg * 256 + cch) * 128 + 2 * hrow + r) * 128 + s2;
#pragma unroll
            for (int nf = 0; nf < 8; nf++) {
                int w0 = nf * 8 + 2 * q;
                rowp[2 * w0]     = acc[mf][nf][which * 2 + 0] + bias;
                rowp[2 * w0 + 2] = acc[mf][nf][which * 2 + 1] + bias;
            }
        }
    }
}

// ---------------------------------------------------------------------------
extern "C" void kernel_launch(void* const* d_in, const int* in_sizes, int n_in,
                              void* d_out, int out_size)
{
    const float* x    = (const float*)d_in[0];
    const float* wq   = (const float*)d_in[1];
    const float* wkv  = (const float*)d_in[2];
    const float* wo   = (const float*)d_in[3];
    const float* bo   = (const float*)d_in[4];
    const float* relh = (const float*)d_in[5];
    const float* relw = (const float*)d_in[6];
    const float* wc   = (const float*)d_in[7];
    const float* bc   = (const float*)d_in[8];
    float* out = (float*)d_out;

    cudaFuncSetAttribute(k_qkv_tc,  cudaFuncAttributeMaxDynamicSharedMemorySize, QK_SMEM);
    cudaFuncSetAttribute(k_attn_tc, cudaFuncAttributeMaxDynamicSharedMemorySize, AT_SMEM);
    cudaFuncSetAttribute(k_out_tc,  cudaFuncAttributeMaxDynamicSharedMemorySize, KO_SMEM);

    k_prep<<<9216, 256>>>(x, wq, wkv, wo, bo, wc, bc);
    k_qkv_tc<<<dim3(256, 6), 256, QK_SMEM>>>();
    k_attn_tc<<<dim3(512, 4), 256, AT_SMEM>>>(relh, relw);
    k_out_tc<<<dim3(256, 8), 256, KO_SMEM>>>(out);
}

// round 16
// speedup vs baseline: 1.0868x; 1.0293x over previous
#include <cuda_runtime.h>
#include <cuda_fp16.h>
#include <stdint.h>

#define NPIX 32768            // B*H*W
#define QKVC 768

// Scratch (device globals; 16B-aligned)
__device__ __align__(16) __half g_qh[NPIX * QKVC];  // qkv fp16, [pixel][q|k|v]
__device__ __align__(16) __half g_bh[NPIX * 256];   // attn out fp16, [n][256]
__device__ __align__(16) __half g_wfh[1024 * 256];  // fused conv W fp16, [m][k]
__device__ __align__(16) __half g_wqh[QKVC * 256];  // qkv W fp16 (q pre-scaled), [m][k]
__device__ __align__(16) __half g_xh[256 * NPIX];   // x fp16, [k][n]
__device__ float g_bf[1024];

// ---------------------------------------------------------------------------
// helpers (non-arch-specific PTX only: cp.async / ldmatrix / mma.sync)
// ---------------------------------------------------------------------------
__device__ __forceinline__ uint32_t smem_u32(const void* p) {
    uint32_t a;
    asm("{ .reg .u64 t; cvta.to.shared.u64 t, %1; cvt.u32.u64 %0, t; }" : "=r"(a) : "l"(p));
    return a;
}
__device__ __forceinline__ void cp16(uint32_t d, const void* s) {
    asm volatile("cp.async.cg.shared.global [%0], [%1], 16;" :: "r"(d), "l"(s));
}
__device__ __forceinline__ void cp16z(uint32_t d, const void* s, uint32_t sz) {
    asm volatile("cp.async.cg.shared.global [%0], [%1], 16, %2;" :: "r"(d), "l"(s), "r"(sz));
}
#define CP_COMMIT() asm volatile("cp.async.commit_group;")
#define CP_WAIT2()  asm volatile("cp.async.wait_group 2;")
#define CP_WAIT1()  asm volatile("cp.async.wait_group 1;")
#define CP_WAIT0()  asm volatile("cp.async.wait_group 0;")

__device__ __forceinline__ void ldm4(uint32_t* r, uint32_t a) {
    asm volatile("ldmatrix.sync.aligned.m8n8.x4.shared.b16 {%0,%1,%2,%3}, [%4];"
                 : "=r"(r[0]), "=r"(r[1]), "=r"(r[2]), "=r"(r[3]) : "r"(a));
}
__device__ __forceinline__ void ldm4t(uint32_t* r, uint32_t a) {
    asm volatile("ldmatrix.sync.aligned.m8n8.x4.trans.shared.b16 {%0,%1,%2,%3}, [%4];"
                 : "=r"(r[0]), "=r"(r[1]), "=r"(r[2]), "=r"(r[3]) : "r"(a));
}
__device__ __forceinline__ void mma_f16(float* d, const uint32_t* a, uint32_t b0, uint32_t b1) {
    asm volatile("mma.sync.aligned.m16n8k16.row.col.f32.f16.f16.f32 "
                 "{%0,%1,%2,%3}, {%4,%5,%6,%7}, {%8,%9}, {%0,%1,%2,%3};"
                 : "+f"(d[0]), "+f"(d[1]), "+f"(d[2]), "+f"(d[3])
                 : "r"(a[0]), "r"(a[1]), "r"(a[2]), "r"(a[3]), "r"(b0), "r"(b1));
}
__device__ __forceinline__ uint32_t packh(__half a, __half b) {
    return (uint32_t)__half_as_ushort(a) | ((uint32_t)__half_as_ushort(b) << 16);
}

// ---------------------------------------------------------------------------
// K0: merged prep. blocks [0,8192): split x; [8192,8960): split wq/wkv;
// [8960,9216): fuse wo into conv.
// ---------------------------------------------------------------------------
__global__ __launch_bounds__(256) void k_prep(const float* __restrict__ x,
                                              const float* __restrict__ wq,
                                              const float* __restrict__ wkv,
                                              const float* __restrict__ wo,
                                              const float* __restrict__ bo,
                                              const float* __restrict__ wc,
                                              const float* __restrict__ bc)
{
    int b = blockIdx.x;
    if (b < 8192) {
        size_t i = (size_t)(b * 256 + threadIdx.x) * 4;
        float4 v = *(const float4*)(x + i);
        size_t o = (size_t)((i >> 12) & 255) * NPIX + ((i >> 20) << 12) + (i & 4095);
        *(uint2*)&g_xh[o] = make_uint2(packh(__float2half_rn(v.x), __float2half_rn(v.y)),
                                       packh(__float2half_rn(v.z), __float2half_rn(v.w)));
    } else if (b < 8960) {
        int i = (b - 8192) * 256 + threadIdx.x;
        int m = i >> 8, c = i & 255;
        float v = (m < 256) ? wq[m * 256 + c] * 0.125f : wkv[(m - 256) * 256 + c];
        g_wqh[i] = __float2half_rn(v);
    } else {
        int ob = (b - 8960) * 4;
        int i  = threadIdx.x;
        float a0 = 0.f, a1 = 0.f, a2 = 0.f, a3 = 0.f;
        for (int cc = 0; cc < 256; cc++) {
            float w = wo[cc * 256 + i];
            a0 += wc[(ob + 0) * 256 + cc] * w;
            a1 += wc[(ob + 1) * 256 + cc] * w;
            a2 += wc[(ob + 2) * 256 + cc] * w;
            a3 += wc[(ob + 3) * 256 + cc] * w;
        }
        float vals[4] = {a0, a1, a2, a3};
#pragma unroll
        for (int j = 0; j < 4; j++)
            g_wfh[(size_t)(ob + j) * 256 + i] = __float2half_rn(vals[j]);
        if (i < 4) {
            int o = ob + i;
            float s = 0.f;
            for (int c2 = 0; c2 < 256; c2++) s += wc[o * 256 + c2] * bo[c2];
            g_bf[o] = s + bc[o];
        }
    }
}

// ---------------------------------------------------------------------------
// K1: QKV projection. C[768,32768] = W @ X, fp16 single-term.
// k=32 stages (8 total), 4-stage cp.async.cg ring, fully unrolled.
// ---------------------------------------------------------------------------
#define QK_BUF  18944
#define QK_SMEM (QK_BUF * 4)

__global__ void __launch_bounds__(256, 2) k_qkv_tc()
{
    extern __shared__ char qsm[];
    uint32_t base = smem_u32(qsm);
    int tid = threadIdx.x, lane = tid & 31, wrp = tid >> 5;
    int wm = wrp >> 1, wn = wrp & 1;
    int mt = blockIdx.y, n0 = blockIdx.x << 7;
    int m0 = mt << 7;

    float acc[2][8][4];
#pragma unroll
    for (int a = 0; a < 2; a++)
#pragma unroll
        for (int b = 0; b < 8; b++)
#pragma unroll
            for (int c = 0; c < 4; c++) acc[a][b][c] = 0.f;

    int ar = tid >> 1, ac = (tid & 1) << 4;
    int br = tid >> 3, bc = (tid & 7) << 4;

    auto issue = [&](int s, int buf) {
        int kk = s << 5;
        uint32_t qa = base + buf * QK_BUF;
        const __half* A = g_wqh + (size_t)(m0 + ar) * 256 + kk + ac;
        uint32_t da = qa + ((ar * 40 + ac) << 1);
        cp16(da, A); cp16(da + 16, A + 8);
        const __half* B = g_xh + (size_t)(kk + br) * NPIX + n0 + bc;
        uint32_t db = qa + 10240 + ((br * 136 + bc) << 1);
        cp16(db, B); cp16(db + 16, B + 8);
    };
    auto compute = [&](int buf) {
        uint32_t qa = base + buf * QK_BUF;
        uint32_t ab = qa, bb = qa + 10240;
#pragma unroll
        for (int kh = 0; kh < 32; kh += 16) {
            uint32_t ah[2][4];
#pragma unroll
            for (int mf = 0; mf < 2; mf++)
                ldm4(ah[mf], ab + (((wm * 32 + mf * 16 + (lane & 15)) * 40
                                   + kh + ((lane >> 4) << 3)) << 1));
#pragma unroll
            for (int nb = 0; nb < 4; nb++) {
                uint32_t bh4[4];
                ldm4t(bh4, bb + (((kh + ((lane >> 3) & 1) * 8 + (lane & 7)) * 136
                                  + wn * 64 + nb * 16 + ((lane >> 4) << 3)) << 1));
#pragma unroll
                for (int mf = 0; mf < 2; mf++) {
                    mma_f16(acc[mf][nb * 2],     ah[mf], bh4[0], bh4[1]);
                    mma_f16(acc[mf][nb * 2 + 1], ah[mf], bh4[2], bh4[3]);
                }
            }
        }
    };

    issue(0, 0); CP_COMMIT();
    issue(1, 1); CP_COMMIT();
    issue(2, 2); CP_COMMIT();
#pragma unroll
    for (int s = 0; s < 8; s++) {
        if (s < 6) CP_WAIT2();
        else if (s == 6) CP_WAIT1();
        else CP_WAIT0();
        __syncthreads();
        if (s + 3 < 8) { issue(s + 3, (s + 3) & 3); CP_COMMIT(); }
        compute(s & 3);
    }
    __syncthreads();

    // epilogue: transpose per 32-row m-quarter via smem; write fp16
    float* tb = (float*)qsm;
    int g = lane >> 2, q = lane & 3;
#pragma unroll
    for (int mq = 0; mq < 4; mq++) {
        if (wm == mq) {
#pragma unroll
            for (int mf = 0; mf < 2; mf++)
#pragma unroll
                for (int nf = 0; nf < 8; nf++) {
                    int nl = wn * 64 + nf * 8 + q * 2;
                    int ml = mf * 16 + g;
                    tb[nl * 33 + ml]            = acc[mf][nf][0];
                    tb[(nl + 1) * 33 + ml]      = acc[mf][nf][1];
                    tb[nl * 33 + ml + 8]        = acc[mf][nf][2];
                    tb[(nl + 1) * 33 + ml + 8]  = acc[mf][nf][3];
                }
        }
        __syncthreads();
        int nl = tid >> 1, half2 = tid & 1;
        const float* src = tb + nl * 33 + half2 * 16;
        size_t dst = (size_t)(n0 + nl) * QKVC + m0 + mq * 32 + half2 * 16;
        unsigned short hs[16];
#pragma unroll
        for (int u = 0; u < 16; u++)
            hs[u] = __half_as_ushort(__float2half_rn(src[u]));
        *(uint4*)&g_qh[dst]     = *(uint4*)&hs[0];
        *(uint4*)&g_qh[dst + 8] = *(uint4*)&hs[8];
        __syncthreads();
    }
}

// ---------------------------------------------------------------------------
// K2: tensor-core halo attention (R13 version, unchanged).
// ---------------------------------------------------------------------------
#define AT_SQ    0
#define AT_SK    9216
#define AT_RELH  46080
#define AT_RELW  50688
#define AT_GW    55296
#define AT_GH    63744
#define AT_RMX   72192
#define AT_RSUM  72704
#define AT_RED2  73216
#define AT_SMEM  90624

__global__ void __launch_bounds__(256, 2) k_attn_tc(const float* __restrict__ relh,
                                                    const float* __restrict__ relw)
{
    extern __shared__ char smc[];
    uint32_t sb = smem_u32(smc);
    int t = threadIdx.x, lane = t & 31, wid = t >> 5;
    int wm = wid >> 1, wn = wid & 1;
    int nbk = blockIdx.x, hh = blockIdx.y;
    int bi = nbk >> 6, tbw = nbk & 63;
    int bh = tbw >> 3, bw = tbw & 7;
    int hco = hh * 64;

    uint32_t qB = sb + AT_SQ;
    uint32_t kB = sb + AT_SK;

    {
        int chunk = t & 7, rr = t >> 3;
        {
            int row = rr;
            int qx = row >> 3, qy = row & 7;
            size_t pix = (size_t)(bi * 4096 + (bh * 8 + qx) * 64 + bw * 8 + qy) * QKVC + hco;
            cp16(qB + ((uint32_t)(row * 9 + chunk) << 4), g_qh + pix + chunk * 8);
            row = rr + 32;
            qx = row >> 3; qy = row & 7;
            pix = (size_t)(bi * 4096 + (bh * 8 + qx) * 64 + bw * 8 + qy) * QKVC + hco;
            cp16(qB + ((uint32_t)(row * 9 + chunk) << 4), g_qh + pix + chunk * 8);
        }
#pragma unroll
        for (int p = 0; p < 8; p++) {
            int row = p * 32 + rr;
            int ki = row >> 4, kj = row & 15;
            int gh = bh * 8 - 4 + ki, gw = bw * 8 - 4 + kj;
            bool valid = ((unsigned)gh < 64u) && ((unsigned)gw < 64u);
            size_t pix = (size_t)(valid ? bi * 4096 + gh * 64 + gw : bi * 4096) * QKVC
                       + 256 + hco + chunk * 8;
            cp16z(kB + ((uint32_t)(row * 9 + chunk) << 4), g_qh + pix, valid ? 16u : 0u);
        }
        CP_COMMIT();
        for (int idx = t; idx < 1152; idx += 256) {
            ((uint32_t*)(smc + AT_RELH))[idx] = 0;
            ((uint32_t*)(smc + AT_RELW))[idx] = 0;
        }
        __syncthreads();
        for (int idx = t; idx < 1984; idx += 256) {
            int r = idx >> 6, dd = idx & 63;
            ((__half*)(smc + AT_RELH))[r * 72 + dd] = __float2half_rn(relh[idx]);
            ((__half*)(smc + AT_RELW))[r * 72 + dd] = __float2half_rn(relw[idx]);
        }
        CP_WAIT0();
    }
    __syncthreads();

    // ---- rel logits via MMA: wn==0 -> Gw, wn==1 -> Gh ----
    {
        float racc[4][4];
#pragma unroll
        for (int a = 0; a < 4; a++)
#pragma unroll
            for (int b = 0; b < 4; b++) racc[a][b] = 0.f;
        uint32_t relB = sb + (wn ? AT_RELH : AT_RELW);
#pragma unroll
        for (int kt = 0; kt < 4; kt++) {
            uint32_t ah[4];
            ldm4(ah, qB + (((wm * 16 + (lane & 15)) * 72 + kt * 16 + ((lane >> 4) << 3)) << 1));
#pragma unroll
            for (int nb = 0; nb < 2; nb++) {
                uint32_t bh4[4];
                ldm4(bh4, relB + (((nb * 16 + ((lane >> 4) << 3) + (lane & 7)) * 72
                                   + kt * 16 + (((lane >> 3) & 1) << 3)) << 1));
                mma_f16(racc[nb * 2],     ah, bh4[0], bh4[1]);
                mma_f16(racc[nb * 2 + 1], ah, bh4[2], bh4[3]);
            }
        }
        float* G = (float*)(smc + (wn ? AT_GH : AT_GW));
        int g2 = lane >> 2, tt = lane & 3;
#pragma unroll
        for (int j = 0; j < 4; j++)
#pragma unroll
            for (int e = 0; e < 4; e++) {
                int row = wm * 16 + g2 + ((e >= 2) ? 8 : 0);
                int col = j * 8 + 2 * tt + (e & 1);
                G[row * 33 + col] = racc[j][e];
            }
    }

    // ---- QK^T ----
    float s[16][4];
#pragma unroll
    for (int a = 0; a < 16; a++)
#pragma unroll
        for (int b = 0; b < 4; b++) s[a][b] = 0.f;
#pragma unroll
    for (int kt = 0; kt < 4; kt++) {
        uint32_t ah[4];
        ldm4(ah, qB + (((wm * 16 + (lane & 15)) * 72 + kt * 16 + ((lane >> 4) << 3)) << 1));
#pragma unroll
        for (int nb = 0; nb < 8; nb++) {
            uint32_t boff = (((wn * 128 + nb * 16 + ((lane >> 4) << 3) + (lane & 7)) * 72
                             + kt * 16 + (((lane >> 3) & 1) << 3)) << 1);
            uint32_t bh4[4];
            ldm4(bh4, kB + boff);
            mma_f16(s[nb * 2],     ah, bh4[0], bh4[1]);
            mma_f16(s[nb * 2 + 1], ah, bh4[2], bh4[3]);
        }
    }
    __syncthreads();

    // ---- prefetch V into K buffer ----
    {
        int chunk = t & 7, rr = t >> 3;
#pragma unroll
        for (int p = 0; p < 8; p++) {
            int row = p * 32 + rr;
            int ki = row >> 4, kj = row & 15;
            int gh = bh * 8 - 4 + ki, gw = bw * 8 - 4 + kj;
            bool valid = ((unsigned)gh < 64u) && ((unsigned)gw < 64u);
            size_t pix = (size_t)(valid ? bi * 4096 + gh * 64 + gw : bi * 4096) * QKVC
                       + 512 + hco + chunk * 8;
            cp16z(kB + ((uint32_t)(row * 9 + chunk) << 4), g_qh + pix, valid ? 16u : 0u);
        }
        CP_COMMIT();
    }

    // ---- fixup: rel logits + mask ----
    {
        const float* Gw = (const float*)(smc + AT_GW);
        const float* Gh = (const float*)(smc + AT_GH);
        int g = lane >> 2, tt = lane & 3;
#pragma unroll
        for (int nt = 0; nt < 16; nt++) {
            int jbase = wn * 128 + nt * 8 + 2 * tt;
#pragma unroll
            for (int e = 0; e < 4; e++) {
                int row = wm * 16 + g + ((e >= 2) ? 8 : 0);
                int jj = jbase + (e & 1);
                int ki = jj >> 4, kj = jj & 15;
                int gh = bh * 8 - 4 + ki, gw = bw * 8 - 4 + kj;
                if (((unsigned)gh >= 64u) || ((unsigned)gw >= 64u))
                    s[nt][e] = -3.0e38f;
                else
                    s[nt][e] += Gw[row * 33 + kj - (row & 7) + 15]
                              + Gh[row * 33 + ki - (row >> 3) + 15];
            }
        }
    }

    float* rmx  = (float*)(smc + AT_RMX);
    float* rsum = (float*)(smc + AT_RSUM);
    int gg = lane >> 2;
    int rA = wm * 16 + gg, rB = rA + 8;
    {
        float mA = -3.4e38f, mB = -3.4e38f;
#pragma unroll
        for (int nt = 0; nt < 16; nt++) {
            mA = fmaxf(mA, fmaxf(s[nt][0], s[nt][1]));
            mB = fmaxf(mB, fmaxf(s[nt][2], s[nt][3]));
        }
        mA = fmaxf(mA, __shfl_xor_sync(0xffffffffu, mA, 1));
        mA = fmaxf(mA, __shfl_xor_sync(0xffffffffu, mA, 2));
        mB = fmaxf(mB, __shfl_xor_sync(0xffffffffu, mB, 1));
        mB = fmaxf(mB, __shfl_xor_sync(0xffffffffu, mB, 2));
        if ((lane & 3) == 0) { rmx[wn * 64 + rA] = mA; rmx[wn * 64 + rB] = mB; }
    }
    __syncthreads();
    {
        float mA = fmaxf(rmx[rA], rmx[64 + rA]);
        float mB = fmaxf(rmx[rB], rmx[64 + rB]);
        float sA = 0.f, sB = 0.f;
#pragma unroll
        for (int nt = 0; nt < 16; nt++) {
            s[nt][0] = __expf(s[nt][0] - mA); sA += s[nt][0];
            s[nt][1] = __expf(s[nt][1] - mA); sA += s[nt][1];
            s[nt][2] = __expf(s[nt][2] - mB); sB += s[nt][2];
            s[nt][3] = __expf(s[nt][3] - mB); sB += s[nt][3];
        }
        sA += __shfl_xor_sync(0xffffffffu, sA, 1);
        sA += __shfl_xor_sync(0xffffffffu, sA, 2);
        sB += __shfl_xor_sync(0xffffffffu, sB, 1);
        sB += __shfl_xor_sync(0xffffffffu, sB, 2);
        if ((lane & 3) == 0) { rsum[wn * 64 + rA] = sA; rsum[wn * 64 + rB] = sB; }
    }
    __syncthreads();
    {
        float invA = 1.0f / (rsum[rA] + rsum[64 + rA]);
        float invB = 1.0f / (rsum[rB] + rsum[64 + rB]);
#pragma unroll
        for (int nt = 0; nt < 16; nt++) {
            __half h0 = __float2half_rn(s[nt][0] * invA);
            __half h1 = __float2half_rn(s[nt][1] * invA);
            __half h2 = __float2half_rn(s[nt][2] * invB);
            __half h3 = __float2half_rn(s[nt][3] * invB);
            s[nt][0] = __uint_as_float(packh(h0, h1));
            s[nt][1] = __uint_as_float(packh(h2, h3));
        }
    }
    CP_WAIT0();
    __syncthreads();

    // ---- AV ----
    float avc[8][4];
#pragma unroll
    for (int a = 0; a < 8; a++)
#pragma unroll
        for (int b = 0; b < 4; b++) avc[a][b] = 0.f;
#pragma unroll
    for (int kt2 = 0; kt2 < 8; kt2++) {
        uint32_t pa[4] = { __float_as_uint(s[2 * kt2][0]), __float_as_uint(s[2 * kt2][1]),
                           __float_as_uint(s[2 * kt2 + 1][0]), __float_as_uint(s[2 * kt2 + 1][1]) };
#pragma unroll
        for (int nb = 0; nb < 4; nb++) {
            uint32_t off = (((wn * 128 + kt2 * 16 + ((lane >> 3) & 1) * 8 + (lane & 7)) * 72
                            + nb * 16 + ((lane >> 4) << 3)) << 1);
            uint32_t vh4[4];
            ldm4t(vh4, kB + off);
            mma_f16(avc[nb * 2],     pa, vh4[0], vh4[1]);
            mma_f16(avc[nb * 2 + 1], pa, vh4[2], vh4[3]);
        }
    }

    // dual-buffer reduction: wn==0 -> Red1 (overlays sK), wn==1 -> Red2
    float* Red1 = (float*)(smc + AT_SK);
    float* Red2 = (float*)(smc + AT_RED2);
    __syncthreads();
    {
        float* Rd = wn ? Red2 : Red1;
#pragma unroll
        for (int nf = 0; nf < 8; nf++)
#pragma unroll
            for (int e = 0; e < 4; e++) {
                int row = wm * 16 + gg + ((e >= 2) ? 8 : 0);
                int col = nf * 8 + 2 * (lane & 3) + (e & 1);
                Rd[row * 68 + col] = avc[nf][e];
            }
    }
    __syncthreads();

    {
        int qi = t >> 2, c0 = (t & 3) * 16;
        int qx = qi >> 3, qy = qi & 7;
        size_t base = (size_t)(bi * 4096 + (bh * 8 + qx) * 64 + bw * 8 + qy) * 256 + hco + c0;
        unsigned short hs[16];
#pragma unroll
        for (int u = 0; u < 16; u++)
            hs[u] = __half_as_ushort(__float2half_rn(Red1[qi * 68 + c0 + u]
                                                   + Red2[qi * 68 + c0 + u]));
        *(uint4*)&g_bh[base]     = *(uint4*)&hs[0];
        *(uint4*)&g_bh[base + 8] = *(uint4*)&hs[8];
    }
}

// ---------------------------------------------------------------------------
// K3: output GEMM + PixelShuffle. k=32 stages, 4-stage cg ring, unrolled.
// Epilogue: shfl-pack interleaved columns -> float4 stores.
// ---------------------------------------------------------------------------
#define KO_BUF  20480
#define KO_SMEM (KO_BUF * 4)

__global__ void __launch_bounds__(256, 2) k_out_tc(float* __restrict__ out)
{
    extern __shared__ char osm[];
    uint32_t base = smem_u32(osm);
    int tid = threadIdx.x, lane = tid & 31, wrp = tid >> 5;
    int wm = wrp >> 1, wn = wrp & 1;
    int mt = blockIdx.y, n0 = blockIdx.x << 7;
    int m0 = mt << 7;

    float acc[2][8][4];
#pragma unroll
    for (int a = 0; a < 2; a++)
#pragma unroll
        for (int b = 0; b < 8; b++)
#pragma unroll
            for (int c = 0; c < 4; c++) acc[a][b][c] = 0.f;

    int ar = tid >> 1, ac = (tid & 1) << 4;

    auto issue = [&](int s, int buf) {
        int kk = s << 5;
        uint32_t qa = base + buf * KO_BUF;
        const __half* A = g_wfh + (size_t)(m0 + ar) * 256 + kk + ac;
        uint32_t da = qa + ((ar * 40 + ac) << 1);
        cp16(da, A); cp16(da + 16, A + 8);
        const __half* B = g_bh + (size_t)(n0 + ar) * 256 + kk + ac;
        uint32_t db = qa + 10240 + ((ar * 40 + ac) << 1);
        cp16(db, B); cp16(db + 16, B + 8);
    };
    auto compute = [&](int buf) {
        uint32_t qa = base + buf * KO_BUF;
        uint32_t ab = qa, bb = qa + 10240;
#pragma unroll
        for (int kh = 0; kh < 32; kh += 16) {
            uint32_t ah[2][4];
#pragma unroll
            for (int mf = 0; mf < 2; mf++)
                ldm4(ah[mf], ab + (((wm * 32 + mf * 16 + (lane & 15)) * 40
                                   + kh + ((lane >> 4) << 3)) << 1));
#pragma unroll
            for (int nb = 0; nb < 4; nb++) {
                uint32_t bh4[4];
                ldm4(bh4, bb + (((wn * 64 + nb * 16 + ((lane >> 4) << 3) + (lane & 7)) * 40
                                 + kh + (((lane >> 3) & 1) << 3)) << 1));
#pragma unroll
                for (int mf = 0; mf < 2; mf++) {
                    mma_f16(acc[mf][nb * 2],     ah[mf], bh4[0], bh4[1]);
                    mma_f16(acc[mf][nb * 2 + 1], ah[mf], bh4[2], bh4[3]);
                }
            }
        }
    };

    issue(0, 0); CP_COMMIT();
    issue(1, 1); CP_COMMIT();
    issue(2, 2); CP_COMMIT();
#pragma unroll
    for (int s = 0; s < 8; s++) {
        if (s < 6) CP_WAIT2();
        else if (s == 6) CP_WAIT1();
        else CP_WAIT0();
        __syncthreads();
        if (s + 3 < 8) { issue(s + 3, (s + 3) & 3); CP_COMMIT(); }
        compute(s & 3);
    }

    // ---- epilogue: shfl-pack (lanes l <-> l^4 hold even/odd cols of the
    // same output row) -> one float4 store per (mf, nf) per lane.
    // Even-g lanes store the which=0 row, odd-g lanes the which=1 row.
    int g = lane >> 2, q = lane & 3;
    int h0 = (n0 & 4095) >> 6, bimg = n0 >> 12;
    int hrow = h0 + wn;
    int p = g & 1;
    float bias0 = g_bf[m0 + wm * 32 + 0 * 16 + g + 0];      // mf=0, which=0
    float bias1 = g_bf[m0 + wm * 32 + 0 * 16 + g + 8];      // mf=0, which=1
    float bias2 = g_bf[m0 + wm * 32 + 1 * 16 + g + 0];      // mf=1, which=0
    float bias3 = g_bf[m0 + wm * 32 + 1 * 16 + g + 8];      // mf=1, which=1
#pragma unroll
    for (int mf = 0; mf < 2; mf++) {
        float bw0 = mf ? bias2 : bias0;
        float bw1 = mf ? bias3 : bias1;
        // row this lane stores: which = p
        int mmrow = m0 + wm * 32 + mf * 16 + (g & ~1) + p * 8;
        int cch = mmrow >> 2, r = (mmrow >> 1) & 1;
        float* rowp = out + ((size_t)(bimg * 256 + cch) * 128 + 2 * hrow + r) * 128;
#pragma unroll
        for (int nf = 0; nf < 8; nf++) {
            float w0v0 = acc[mf][nf][0] + bw0;
            float w0v1 = acc[mf][nf][1] + bw0;
            float w1v0 = acc[mf][nf][2] + bw1;
            float w1v1 = acc[mf][nf][3] + bw1;
            float r00 = __shfl_xor_sync(0xffffffffu, w0v0, 4);
            float r01 = __shfl_xor_sync(0xffffffffu, w0v1, 4);
            float r10 = __shfl_xor_sync(0xffffffffu, w1v0, 4);
            float r11 = __shfl_xor_sync(0xffffffffu, w1v1, 4);
            int colbase = 16 * nf + 4 * q;
            float4 v;
            if (p == 0)  v = make_float4(w0v0, r00, w0v1, r01);   // which=0 row
            else         v = make_float4(r10, w1v0, r11, w1v1);   // which=1 row
            *(float4*)(rowp + colbase) = v;
        }
    }
}

// ---------------------------------------------------------------------------
extern "C" void kernel_launch(void* const* d_in, const int* in_sizes, int n_in,
                              void* d_out, int out_size)
{
    const float* x    = (const float*)d_in[0];
    const float* wq   = (const float*)d_in[1];
    const float* wkv  = (const float*)d_in[2];
    const float* wo   = (const float*)d_in[3];
    const float* bo   = (const float*)d_in[4];
    const float* relh = (const float*)d_in[5];
    const float* relw = (const float*)d_in[6];
    const float* wc   = (const float*)d_in[7];
    const float* bc   = (const float*)d_in[8];
    float* out = (float*)d_out;

    cudaFuncSetAttribute(k_qkv_tc,  cudaFuncAttributeMaxDynamicSharedMemorySize, QK_SMEM);
    cudaFuncSetAttribute(k_attn_tc, cudaFuncAttributeMaxDynamicSharedMemorySize, AT_SMEM);
    cudaFuncSetAttribute(k_out_tc,  cudaFuncAttributeMaxDynamicSharedMemorySize, KO_SMEM);

    k_prep<<<9216, 256>>>(x, wq, wkv, wo, bo, wc, bc);
    k_qkv_tc<<<dim3(256, 6), 256, QK_SMEM>>>();
    k_attn_tc<<<dim3(512, 4), 256, AT_SMEM>>>(relh, relw);
    k_out_tc<<<dim3(256, 8), 256, KO_SMEM>>>(out);
}

// round 17
// speedup vs baseline: 1.1807x; 1.0864x over previous
#include <cuda_runtime.h>
#include <cuda_fp16.h>
#include <stdint.h>

#define NPIX 32768            // B*H*W
#define QKVC 768

// Scratch (device globals; 16B-aligned)
__device__ __align__(16) __half g_qh[NPIX * QKVC];  // qkv fp16, [pixel][q|k|v]
__device__ __align__(16) __half g_bh[NPIX * 256];   // attn out fp16, [n][256]
__device__ __align__(16) __half g_wfh[1024 * 256];  // fused conv W fp16, [m][k]
__device__ __align__(16) __half g_wqh[QKVC * 256];  // qkv W fp16 (q pre-scaled), [m][k]
__device__ __align__(16) __half g_xh[256 * NPIX];   // x fp16, [k][n]
__device__ float g_bf[1024];

// ---------------------------------------------------------------------------
// helpers (non-arch-specific PTX only: cp.async / ldmatrix / mma.sync)
// ---------------------------------------------------------------------------
__device__ __forceinline__ uint32_t smem_u32(const void* p) {
    uint32_t a;
    asm("{ .reg .u64 t; cvta.to.shared.u64 t, %1; cvt.u32.u64 %0, t; }" : "=r"(a) : "l"(p));
    return a;
}
__device__ __forceinline__ void cp16(uint32_t d, const void* s) {
    asm volatile("cp.async.cg.shared.global [%0], [%1], 16;" :: "r"(d), "l"(s));
}
__device__ __forceinline__ void cp16z(uint32_t d, const void* s, uint32_t sz) {
    asm volatile("cp.async.cg.shared.global [%0], [%1], 16, %2;" :: "r"(d), "l"(s), "r"(sz));
}
#define CP_COMMIT() asm volatile("cp.async.commit_group;")
#define CP_WAIT2()  asm volatile("cp.async.wait_group 2;")
#define CP_WAIT1()  asm volatile("cp.async.wait_group 1;")
#define CP_WAIT0()  asm volatile("cp.async.wait_group 0;")

__device__ __forceinline__ void ldm4(uint32_t* r, uint32_t a) {
    asm volatile("ldmatrix.sync.aligned.m8n8.x4.shared.b16 {%0,%1,%2,%3}, [%4];"
                 : "=r"(r[0]), "=r"(r[1]), "=r"(r[2]), "=r"(r[3]) : "r"(a));
}
__device__ __forceinline__ void ldm4t(uint32_t* r, uint32_t a) {
    asm volatile("ldmatrix.sync.aligned.m8n8.x4.trans.shared.b16 {%0,%1,%2,%3}, [%4];"
                 : "=r"(r[0]), "=r"(r[1]), "=r"(r[2]), "=r"(r[3]) : "r"(a));
}
__device__ __forceinline__ void mma_f16(float* d, const uint32_t* a, uint32_t b0, uint32_t b1) {
    asm volatile("mma.sync.aligned.m16n8k16.row.col.f32.f16.f16.f32 "
                 "{%0,%1,%2,%3}, {%4,%5,%6,%7}, {%8,%9}, {%0,%1,%2,%3};"
                 : "+f"(d[0]), "+f"(d[1]), "+f"(d[2]), "+f"(d[3])
                 : "r"(a[0]), "r"(a[1]), "r"(a[2]), "r"(a[3]), "r"(b0), "r"(b1));
}
__device__ __forceinline__ uint32_t packh(__half a, __half b) {
    return (uint32_t)__half_as_ushort(a) | ((uint32_t)__half_as_ushort(b) << 16);
}

// ---------------------------------------------------------------------------
// K0: merged prep. blocks [0,8192): split x; [8192,8960): split wq/wkv;
// [8960,9216): fuse wo into conv.
// ---------------------------------------------------------------------------
__global__ __launch_bounds__(256) void k_prep(const float* __restrict__ x,
                                              const float* __restrict__ wq,
                                              const float* __restrict__ wkv,
                                              const float* __restrict__ wo,
                                              const float* __restrict__ bo,
                                              const float* __restrict__ wc,
                                              const float* __restrict__ bc)
{
    int b = blockIdx.x;
    if (b < 8192) {
        size_t i = (size_t)(b * 256 + threadIdx.x) * 4;
        float4 v = *(const float4*)(x + i);
        size_t o = (size_t)((i >> 12) & 255) * NPIX + ((i >> 20) << 12) + (i & 4095);
        *(uint2*)&g_xh[o] = make_uint2(packh(__float2half_rn(v.x), __float2half_rn(v.y)),
                                       packh(__float2half_rn(v.z), __float2half_rn(v.w)));
    } else if (b < 8960) {
        int i = (b - 8192) * 256 + threadIdx.x;
        int m = i >> 8, c = i & 255;
        float v = (m < 256) ? wq[m * 256 + c] * 0.125f : wkv[(m - 256) * 256 + c];
        g_wqh[i] = __float2half_rn(v);
    } else {
        int ob = (b - 8960) * 4;
        int i  = threadIdx.x;
        float a0 = 0.f, a1 = 0.f, a2 = 0.f, a3 = 0.f;
        for (int cc = 0; cc < 256; cc++) {
            float w = wo[cc * 256 + i];
            a0 += wc[(ob + 0) * 256 + cc] * w;
            a1 += wc[(ob + 1) * 256 + cc] * w;
            a2 += wc[(ob + 2) * 256 + cc] * w;
            a3 += wc[(ob + 3) * 256 + cc] * w;
        }
        float vals[4] = {a0, a1, a2, a3};
#pragma unroll
        for (int j = 0; j < 4; j++)
            g_wfh[(size_t)(ob + j) * 256 + i] = __float2half_rn(vals[j]);
        if (i < 4) {
            int o = ob + i;
            float s = 0.f;
            for (int c2 = 0; c2 < 256; c2++) s += wc[o * 256 + c2] * bo[c2];
            g_bf[o] = s + bc[o];
        }
    }
}

// ---------------------------------------------------------------------------
// K1: QKV projection. C[768,32768] = W @ X, fp16 single-term.
// k=32 stages (8 total), 4-stage cp.async.cg ring, fully unrolled.
// Single-pass epilogue transpose via [128][132] fp32 buffer over dead ring.
// ---------------------------------------------------------------------------
#define QK_BUF  18944
#define QK_SMEM (QK_BUF * 4)

__global__ void __launch_bounds__(256, 2) k_qkv_tc()
{
    extern __shared__ char qsm[];
    uint32_t base = smem_u32(qsm);
    int tid = threadIdx.x, lane = tid & 31, wrp = tid >> 5;
    int wm = wrp >> 1, wn = wrp & 1;
    int mt = blockIdx.y, n0 = blockIdx.x << 7;
    int m0 = mt << 7;

    float acc[2][8][4];
#pragma unroll
    for (int a = 0; a < 2; a++)
#pragma unroll
        for (int b = 0; b < 8; b++)
#pragma unroll
            for (int c = 0; c < 4; c++) acc[a][b][c] = 0.f;

    int ar = tid >> 1, ac = (tid & 1) << 4;
    int br = tid >> 3, bc = (tid & 7) << 4;

    auto issue = [&](int s, int buf) {
        int kk = s << 5;
        uint32_t qa = base + buf * QK_BUF;
        const __half* A = g_wqh + (size_t)(m0 + ar) * 256 + kk + ac;
        uint32_t da = qa + ((ar * 40 + ac) << 1);
        cp16(da, A); cp16(da + 16, A + 8);
        const __half* B = g_xh + (size_t)(kk + br) * NPIX + n0 + bc;
        uint32_t db = qa + 10240 + ((br * 136 + bc) << 1);
        cp16(db, B); cp16(db + 16, B + 8);
    };
    auto compute = [&](int buf) {
        uint32_t qa = base + buf * QK_BUF;
        uint32_t ab = qa, bb = qa + 10240;
#pragma unroll
        for (int kh = 0; kh < 32; kh += 16) {
            uint32_t ah[2][4];
#pragma unroll
            for (int mf = 0; mf < 2; mf++)
                ldm4(ah[mf], ab + (((wm * 32 + mf * 16 + (lane & 15)) * 40
                                   + kh + ((lane >> 4) << 3)) << 1));
#pragma unroll
            for (int nb = 0; nb < 4; nb++) {
                uint32_t bh4[4];
                ldm4t(bh4, bb + (((kh + ((lane >> 3) & 1) * 8 + (lane & 7)) * 136
                                  + wn * 64 + nb * 16 + ((lane >> 4) << 3)) << 1));
#pragma unroll
                for (int mf = 0; mf < 2; mf++) {
                    mma_f16(acc[mf][nb * 2],     ah[mf], bh4[0], bh4[1]);
                    mma_f16(acc[mf][nb * 2 + 1], ah[mf], bh4[2], bh4[3]);
                }
            }
        }
    };

    issue(0, 0); CP_COMMIT();
    issue(1, 1); CP_COMMIT();
    issue(2, 2); CP_COMMIT();
#pragma unroll
    for (int s = 0; s < 8; s++) {
        if (s < 6) CP_WAIT2();
        else if (s == 6) CP_WAIT1();
        else CP_WAIT0();
        __syncthreads();
        if (s + 3 < 8) { issue(s + 3, (s + 3) & 3); CP_COMMIT(); }
        compute(s & 3);
    }
    __syncthreads();

    // ---- single-pass epilogue transpose: tb[n 0..127][m 0..127], stride 132
    float* tb = (float*)qsm;      // 128*132*4 = 67584 B < 75776 B
    int g = lane >> 2, q = lane & 3;
#pragma unroll
    for (int mf = 0; mf < 2; mf++)
#pragma unroll
        for (int nf = 0; nf < 8; nf++)
#pragma unroll
            for (int e = 0; e < 4; e++) {
                int nl = wn * 64 + nf * 8 + 2 * q + (e & 1);
                int ml = wm * 32 + mf * 16 + g + ((e >= 2) ? 8 : 0);
                tb[nl * 132 + ml] = acc[mf][nf][e];
            }
    __syncthreads();
    {
        int nl = tid >> 1, half2 = tid & 1;
        const float* src = tb + nl * 132 + half2 * 64;
        size_t dst = (size_t)(n0 + nl) * QKVC + m0 + half2 * 64;
#pragma unroll
        for (int hblk = 0; hblk < 2; hblk++) {
            unsigned short hs[32];
#pragma unroll
            for (int u = 0; u < 32; u++)
                hs[u] = __half_as_ushort(__float2half_rn(src[hblk * 32 + u]));
            *(uint4*)&g_qh[dst + hblk * 32]      = *(uint4*)&hs[0];
            *(uint4*)&g_qh[dst + hblk * 32 + 8]  = *(uint4*)&hs[8];
            *(uint4*)&g_qh[dst + hblk * 32 + 16] = *(uint4*)&hs[16];
            *(uint4*)&g_qh[dst + hblk * 32 + 24] = *(uint4*)&hs[24];
        }
    }
}

// ---------------------------------------------------------------------------
// K2: tensor-core halo attention. Fixup loads hoisted (24 LDS/thread).
// ---------------------------------------------------------------------------
#define AT_SQ    0
#define AT_SK    9216
#define AT_RELH  46080
#define AT_RELW  50688
#define AT_GW    55296
#define AT_GH    63744
#define AT_RMX   72192
#define AT_RSUM  72704
#define AT_RED2  73216
#define AT_SMEM  90624

__global__ void __launch_bounds__(256, 2) k_attn_tc(const float* __restrict__ relh,
                                                    const float* __restrict__ relw)
{
    extern __shared__ char smc[];
    uint32_t sb = smem_u32(smc);
    int t = threadIdx.x, lane = t & 31, wid = t >> 5;
    int wm = wid >> 1, wn = wid & 1;
    int nbk = blockIdx.x, hh = blockIdx.y;
    int bi = nbk >> 6, tbw = nbk & 63;
    int bh = tbw >> 3, bw = tbw & 7;
    int hco = hh * 64;

    uint32_t qB = sb + AT_SQ;
    uint32_t kB = sb + AT_SK;

    {
        int chunk = t & 7, rr = t >> 3;
        {
            int row = rr;
            int qx = row >> 3, qy = row & 7;
            size_t pix = (size_t)(bi * 4096 + (bh * 8 + qx) * 64 + bw * 8 + qy) * QKVC + hco;
            cp16(qB + ((uint32_t)(row * 9 + chunk) << 4), g_qh + pix + chunk * 8);
            row = rr + 32;
            qx = row >> 3; qy = row & 7;
            pix = (size_t)(bi * 4096 + (bh * 8 + qx) * 64 + bw * 8 + qy) * QKVC + hco;
            cp16(qB + ((uint32_t)(row * 9 + chunk) << 4), g_qh + pix + chunk * 8);
        }
#pragma unroll
        for (int p = 0; p < 8; p++) {
            int row = p * 32 + rr;
            int ki = row >> 4, kj = row & 15;
            int gh = bh * 8 - 4 + ki, gw = bw * 8 - 4 + kj;
            bool valid = ((unsigned)gh < 64u) && ((unsigned)gw < 64u);
            size_t pix = (size_t)(valid ? bi * 4096 + gh * 64 + gw : bi * 4096) * QKVC
                       + 256 + hco + chunk * 8;
            cp16z(kB + ((uint32_t)(row * 9 + chunk) << 4), g_qh + pix, valid ? 16u : 0u);
        }
        CP_COMMIT();
        for (int idx = t; idx < 1152; idx += 256) {
            ((uint32_t*)(smc + AT_RELH))[idx] = 0;
            ((uint32_t*)(smc + AT_RELW))[idx] = 0;
        }
        __syncthreads();
        for (int idx = t; idx < 1984; idx += 256) {
            int r = idx >> 6, dd = idx & 63;
            ((__half*)(smc + AT_RELH))[r * 72 + dd] = __float2half_rn(relh[idx]);
            ((__half*)(smc + AT_RELW))[r * 72 + dd] = __float2half_rn(relw[idx]);
        }
        CP_WAIT0();
    }
    __syncthreads();

    // ---- rel logits via MMA: wn==0 -> Gw, wn==1 -> Gh ----
    {
        float racc[4][4];
#pragma unroll
        for (int a = 0; a < 4; a++)
#pragma unroll
            for (int b = 0; b < 4; b++) racc[a][b] = 0.f;
        uint32_t relB = sb + (wn ? AT_RELH : AT_RELW);
#pragma unroll
        for (int kt = 0; kt < 4; kt++) {
            uint32_t ah[4];
            ldm4(ah, qB + (((wm * 16 + (lane & 15)) * 72 + kt * 16 + ((lane >> 4) << 3)) << 1));
#pragma unroll
            for (int nb = 0; nb < 2; nb++) {
                uint32_t bh4[4];
                ldm4(bh4, relB + (((nb * 16 + ((lane >> 4) << 3) + (lane & 7)) * 72
                                   + kt * 16 + (((lane >> 3) & 1) << 3)) << 1));
                mma_f16(racc[nb * 2],     ah, bh4[0], bh4[1]);
                mma_f16(racc[nb * 2 + 1], ah, bh4[2], bh4[3]);
            }
        }
        float* G = (float*)(smc + (wn ? AT_GH : AT_GW));
        int g2 = lane >> 2, tt = lane & 3;
#pragma unroll
        for (int j = 0; j < 4; j++)
#pragma unroll
            for (int e = 0; e < 4; e++) {
                int row = wm * 16 + g2 + ((e >= 2) ? 8 : 0);
                int col = j * 8 + 2 * tt + (e & 1);
                G[row * 33 + col] = racc[j][e];
            }
    }

    // ---- QK^T ----
    float s[16][4];
#pragma unroll
    for (int a = 0; a < 16; a++)
#pragma unroll
        for (int b = 0; b < 4; b++) s[a][b] = 0.f;
#pragma unroll
    for (int kt = 0; kt < 4; kt++) {
        uint32_t ah[4];
        ldm4(ah, qB + (((wm * 16 + (lane & 15)) * 72 + kt * 16 + ((lane >> 4) << 3)) << 1));
#pragma unroll
        for (int nb = 0; nb < 8; nb++) {
            uint32_t boff = (((wn * 128 + nb * 16 + ((lane >> 4) << 3) + (lane & 7)) * 72
                             + kt * 16 + (((lane >> 3) & 1) << 3)) << 1);
            uint32_t bh4[4];
            ldm4(bh4, kB + boff);
            mma_f16(s[nb * 2],     ah, bh4[0], bh4[1]);
            mma_f16(s[nb * 2 + 1], ah, bh4[2], bh4[3]);
        }
    }
    __syncthreads();

    // ---- prefetch V into K buffer ----
    {
        int chunk = t & 7, rr = t >> 3;
#pragma unroll
        for (int p = 0; p < 8; p++) {
            int row = p * 32 + rr;
            int ki = row >> 4, kj = row & 15;
            int gh = bh * 8 - 4 + ki, gw = bw * 8 - 4 + kj;
            bool valid = ((unsigned)gh < 64u) && ((unsigned)gw < 64u);
            size_t pix = (size_t)(valid ? bi * 4096 + gh * 64 + gw : bi * 4096) * QKVC
                       + 512 + hco + chunk * 8;
            cp16z(kB + ((uint32_t)(row * 9 + chunk) << 4), g_qh + pix, valid ? 16u : 0u);
        }
        CP_COMMIT();
    }

    // ---- fixup: rel logits + mask (hoisted G loads: 24 LDS/thread) ----
    {
        const float* Gw = (const float*)(smc + AT_GW);
        const float* Gh = (const float*)(smc + AT_GH);
        int g = lane >> 2, tt = lane & 3;
        int c0 = 2 * tt;
        // kj values c0+{0,1,8,9}; ki values wn*8+{0..7}
        bool vC[4], vR[8];
#pragma unroll
        for (int ci = 0; ci < 4; ci++) {
            int kj = c0 + (ci >> 1) * 8 + (ci & 1);
            vC[ci] = ((unsigned)(bw * 8 - 4 + kj) < 64u);
        }
#pragma unroll
        for (int u = 0; u < 8; u++)
            vR[u] = ((unsigned)(bh * 8 - 4 + wn * 8 + u) < 64u);
        float gwv[2][4], ghv[2][8];
#pragma unroll
        for (int r2 = 0; r2 < 2; r2++) {
            int row = wm * 16 + g + r2 * 8;
            int qy = row & 7, qx = row >> 3;
            const float* gwr = Gw + row * 33 + c0 - qy + 15;
            const float* ghr = Gh + row * 33 + wn * 8 - qx + 15;
#pragma unroll
            for (int ci = 0; ci < 4; ci++)
                gwv[r2][ci] = gwr[(ci >> 1) * 8 + (ci & 1)];
#pragma unroll
            for (int u = 0; u < 8; u++)
                ghv[r2][u] = ghr[u];
        }
#pragma unroll
        for (int nt = 0; nt < 16; nt++) {
            int u = nt >> 1;
#pragma unroll
            for (int e = 0; e < 4; e++) {
                int r2 = (e >= 2) ? 1 : 0;
                int ci = (nt & 1) * 2 + (e & 1);
                if (vR[u] && vC[ci])
                    s[nt][e] += gwv[r2][ci] + ghv[r2][u];
                else
                    s[nt][e] = -3.0e38f;
            }
        }
    }

    float* rmx  = (float*)(smc + AT_RMX);
    float* rsum = (float*)(smc + AT_RSUM);
    int gg = lane >> 2;
    int rA = wm * 16 + gg, rB = rA + 8;
    {
        float mA = -3.4e38f, mB = -3.4e38f;
#pragma unroll
        for (int nt = 0; nt < 16; nt++) {
            mA = fmaxf(mA, fmaxf(s[nt][0], s[nt][1]));
            mB = fmaxf(mB, fmaxf(s[nt][2], s[nt][3]));
        }
        mA = fmaxf(mA, __shfl_xor_sync(0xffffffffu, mA, 1));
        mA = fmaxf(mA, __shfl_xor_sync(0xffffffffu, mA, 2));
        mB = fmaxf(mB, __shfl_xor_sync(0xffffffffu, mB, 1));
        mB = fmaxf(mB, __shfl_xor_sync(0xffffffffu, mB, 2));
        if ((lane & 3) == 0) { rmx[wn * 64 + rA] = mA; rmx[wn * 64 + rB] = mB; }
    }
    __syncthreads();
    {
        float mA = fmaxf(rmx[rA], rmx[64 + rA]);
        float mB = fmaxf(rmx[rB], rmx[64 + rB]);
        float sA = 0.f, sB = 0.f;
#pragma unroll
        for (int nt = 0; nt < 16; nt++) {
            s[nt][0] = __expf(s[nt][0] - mA); sA += s[nt][0];
            s[nt][1] = __expf(s[nt][1] - mA); sA += s[nt][1];
            s[nt][2] = __expf(s[nt][2] - mB); sB += s[nt][2];
            s[nt][3] = __expf(s[nt][3] - mB); sB += s[nt][3];
        }
        sA += __shfl_xor_sync(0xffffffffu, sA, 1);
        sA += __shfl_xor_sync(0xffffffffu, sA, 2);
        sB += __shfl_xor_sync(0xffffffffu, sB, 1);
        sB += __shfl_xor_sync(0xffffffffu, sB, 2);
        if ((lane & 3) == 0) { rsum[wn * 64 + rA] = sA; rsum[wn * 64 + rB] = sB; }
    }
    __syncthreads();
    {
        float invA = 1.0f / (rsum[rA] + rsum[64 + rA]);
        float invB = 1.0f / (rsum[rB] + rsum[64 + rB]);
#pragma unroll
        for (int nt = 0; nt < 16; nt++) {
            __half h0 = __float2half_rn(s[nt][0] * invA);
            __half h1 = __float2half_rn(s[nt][1] * invA);
            __half h2 = __float2half_rn(s[nt][2] * invB);
            __half h3 = __float2half_rn(s[nt][3] * invB);
            s[nt][0] = __uint_as_float(packh(h0, h1));
            s[nt][1] = __uint_as_float(packh(h2, h3));
        }
    }
    CP_WAIT0();
    __syncthreads();

    // ---- AV ----
    float avc[8][4];
#pragma unroll
    for (int a = 0; a < 8; a++)
#pragma unroll
        for (int b = 0; b < 4; b++) avc[a][b] = 0.f;
#pragma unroll
    for (int kt2 = 0; kt2 < 8; kt2++) {
        uint32_t pa[4] = { __float_as_uint(s[2 * kt2][0]), __float_as_uint(s[2 * kt2][1]),
                           __float_as_uint(s[2 * kt2 + 1][0]), __float_as_uint(s[2 * kt2 + 1][1]) };
#pragma unroll
        for (int nb = 0; nb < 4; nb++) {
            uint32_t off = (((wn * 128 + kt2 * 16 + ((lane >> 3) & 1) * 8 + (lane & 7)) * 72
                            + nb * 16 + ((lane >> 4) << 3)) << 1);
            uint32_t vh4[4];
            ldm4t(vh4, kB + off);
            mma_f16(avc[nb * 2],     pa, vh4[0], vh4[1]);
            mma_f16(avc[nb * 2 + 1], pa, vh4[2], vh4[3]);
        }
    }

    // dual-buffer reduction: wn==0 -> Red1 (overlays sK), wn==1 -> Red2
    float* Red1 = (float*)(smc + AT_SK);
    float* Red2 = (float*)(smc + AT_RED2);
    __syncthreads();
    {
        float* Rd = wn ? Red2 : Red1;
#pragma unroll
        for (int nf = 0; nf < 8; nf++)
#pragma unroll
            for (int e = 0; e < 4; e++) {
                int row = wm * 16 + gg + ((e >= 2) ? 8 : 0);
                int col = nf * 8 + 2 * (lane & 3) + (e & 1);
                Rd[row * 68 + col] = avc[nf][e];
            }
    }
    __syncthreads();

    {
        int qi = t >> 2, c0 = (t & 3) * 16;
        int qx = qi >> 3, qy = qi & 7;
        size_t base = (size_t)(bi * 4096 + (bh * 8 + qx) * 64 + bw * 8 + qy) * 256 + hco + c0;
        unsigned short hs[16];
#pragma unroll
        for (int u = 0; u < 16; u++)
            hs[u] = __half_as_ushort(__float2half_rn(Red1[qi * 68 + c0 + u]
                                                   + Red2[qi * 68 + c0 + u]));
        *(uint4*)&g_bh[base]     = *(uint4*)&hs[0];
        *(uint4*)&g_bh[base + 8] = *(uint4*)&hs[8];
    }
}

// ---------------------------------------------------------------------------
// K3: output GEMM + PixelShuffle. k=32 stages, 4-stage cg ring, unrolled.
// Epilogue: shfl-pack interleaved columns -> streaming float4 stores.
// ---------------------------------------------------------------------------
#define KO_BUF  20480
#define KO_SMEM (KO_BUF * 4)

__global__ void __launch_bounds__(256, 2) k_out_tc(float* __restrict__ out)
{
    extern __shared__ char osm[];
    uint32_t base = smem_u32(osm);
    int tid = threadIdx.x, lane = tid & 31, wrp = tid >> 5;
    int wm = wrp >> 1, wn = wrp & 1;
    int mt = blockIdx.y, n0 = blockIdx.x << 7;
    int m0 = mt << 7;

    float acc[2][8][4];
#pragma unroll
    for (int a = 0; a < 2; a++)
#pragma unroll
        for (int b = 0; b < 8; b++)
#pragma unroll
            for (int c = 0; c < 4; c++) acc[a][b][c] = 0.f;

    int ar = tid >> 1, ac = (tid & 1) << 4;

    auto issue = [&](int s, int buf) {
        int kk = s << 5;
        uint32_t qa = base + buf * KO_BUF;
        const __half* A = g_wfh + (size_t)(m0 + ar) * 256 + kk + ac;
        uint32_t da = qa + ((ar * 40 + ac) << 1);
        cp16(da, A); cp16(da + 16, A + 8);
        const __half* B = g_bh + (size_t)(n0 + ar) * 256 + kk + ac;
        uint32_t db = qa + 10240 + ((ar * 40 + ac) << 1);
        cp16(db, B); cp16(db + 16, B + 8);
    };
    auto compute = [&](int buf) {
        uint32_t qa = base + buf * KO_BUF;
        uint32_t ab = qa, bb = qa + 10240;
#pragma unroll
        for (int kh = 0; kh < 32; kh += 16) {
            uint32_t ah[2][4];
#pragma unroll
            for (int mf = 0; mf < 2; mf++)
                ldm4(ah[mf], ab + (((wm * 32 + mf * 16 + (lane & 15)) * 40
                                   + kh + ((lane >> 4) << 3)) << 1));
#pragma unroll
            for (int nb = 0; nb < 4; nb++) {
                uint32_t bh4[4];
                ldm4(bh4, bb + (((wn * 64 + nb * 16 + ((lane >> 4) << 3) + (lane & 7)) * 40
                                 + kh + (((lane >> 3) & 1) << 3)) << 1));
#pragma unroll
                for (int mf = 0; mf < 2; mf++) {
                    mma_f16(acc[mf][nb * 2],     ah[mf], bh4[0], bh4[1]);
                    mma_f16(acc[mf][nb * 2 + 1], ah[mf], bh4[2], bh4[3]);
                }
            }
        }
    };

    issue(0, 0); CP_COMMIT();
    issue(1, 1); CP_COMMIT();
    issue(2, 2); CP_COMMIT();
#pragma unroll
    for (int s = 0; s < 8; s++) {
        if (s < 6) CP_WAIT2();
        else if (s == 6) CP_WAIT1();
        else CP_WAIT0();
        __syncthreads();
        if (s + 3 < 8) { issue(s + 3, (s + 3) & 3); CP_COMMIT(); }
        compute(s & 3);
    }

    // ---- epilogue: shfl-pack -> streaming float4 stores
    int g = lane >> 2, q = lane & 3;
    int h0 = (n0 & 4095) >> 6, bimg = n0 >> 12;
    int hrow = h0 + wn;
    int p = g & 1;
    float bias0 = g_bf[m0 + wm * 32 + 0 * 16 + g + 0];
    float bias1 = g_bf[m0 + wm * 32 + 0 * 16 + g + 8];
    float bias2 = g_bf[m0 + wm * 32 + 1 * 16 + g + 0];
    float bias3 = g_bf[m0 + wm * 32 + 1 * 16 + g + 8];
#pragma unroll
    for (int mf = 0; mf < 2; mf++) {
        float bw0 = mf ? bias2 : bias0;
        float bw1 = mf ? bias3 : bias1;
        int mmrow = m0 + wm * 32 + mf * 16 + (g & ~1) + p * 8;
        int cch = mmrow >> 2, r = (mmrow >> 1) & 1;
        float* rowp = out + ((size_t)(bimg * 256 + cch) * 128 + 2 * hrow + r) * 128;
#pragma unroll
        for (int nf = 0; nf < 8; nf++) {
            float w0v0 = acc[mf][nf][0] + bw0;
            float w0v1 = acc[mf][nf][1] + bw0;
            float w1v0 = acc[mf][nf][2] + bw1;
            float w1v1 = acc[mf][nf][3] + bw1;
            float r00 = __shfl_xor_sync(0xffffffffu, w0v0, 4);
            float r01 = __shfl_xor_sync(0xffffffffu, w0v1, 4);
            float r10 = __shfl_xor_sync(0xffffffffu, w1v0, 4);
            float r11 = __shfl_xor_sync(0xffffffffu, w1v1, 4);
            int colbase = 16 * nf + 4 * q;
            float4 v;
            if (p == 0)  v = make_float4(w0v0, r00, w0v1, r01);
            else         v = make_float4(r10, w1v0, r11, w1v1);
            __stcs((float4*)(rowp + colbase), v);
        }
    }
}

// ---------------------------------------------------------------------------
extern "C" void kernel_launch(void* const* d_in, const int* in_sizes, int n_in,
                              void* d_out, int out_size)
{
    const float* x    = (const float*)d_in[0];
    const float* wq   = (const float*)d_in[1];
    const float* wkv  = (const float*)d_in[2];
    const float* wo   = (const float*)d_in[3];
    const float* bo   = (const float*)d_in[4];
    const float* relh = (const float*)d_in[5];
    const float* relw = (const float*)d_in[6];
    const float* wc   = (const float*)d_in[7];
    const float* bc   = (const float*)d_in[8];
    float* out = (float*)d_out;

    cudaFuncSetAttribute(k_qkv_tc,  cudaFuncAttributeMaxDynamicSharedMemorySize, QK_SMEM);
    cudaFuncSetAttribute(k_attn_tc, cudaFuncAttributeMaxDynamicSharedMemorySize, AT_SMEM);
    cudaFuncSetAttribute(k_out_tc,  cudaFuncAttributeMaxDynamicSharedMemorySize, KO_SMEM);

    k_prep<<<9216, 256>>>(x, wq, wkv, wo, bo, wc, bc);
    k_qkv_tc<<<dim3(256, 6), 256, QK_SMEM>>>();
    k_attn_tc<<<dim3(512, 4), 256, AT_SMEM>>>(relh, relw);
    k_out_tc<<<dim3(256, 8), 256, KO_SMEM>>>(out);
}